// round 6
// baseline (speedup 1.0000x reference)
#include <cuda_runtime.h>
#include <cuda_bf16.h>
#include <math.h>

// Problem constants
#define BATCH 2
#define SEQ   2048
#define DMODEL 1024
#define NHEADS 16
#define HDIM  64
#define HALFWIN 64          // keys j in [i, i+64]  (<=65 keys per query)

// Scratch (allocation-free rule: __device__ globals)
__device__ float g_Q[BATCH * NHEADS * SEQ * HDIM];     // 16 MB, [b,h,t,d]
__device__ float g_K[BATCH * NHEADS * SEQ * HDIM];     // 16 MB
__device__ float g_V[BATCH * NHEADS * SEQ * HDIM];     // 16 MB
__device__ float g_attn[BATCH * SEQ * DMODEL];         // 16 MB, [b,t,h*64+d]

// ---------------------------------------------------------------------------
// NT SGEMM: C[m,n] = sum_k A[m,k] * W[n,k] + bias[n]
// A: [M,K] row-major, W: [N,K] row-major. M = 4096 fixed by grid.
// 128x128 block tile, BK=8, 256 threads, 8x8 per-thread microtile.
// mode 0: write C row-major [M,N] (+bias)
// mode 1: QKV scatter: n = c*1024 + h*64 + d  ->  g_{Q,K,V}[b,h,t,d] (+bias)
// ---------------------------------------------------------------------------
__global__ __launch_bounds__(256) void sgemm_nt(
    const float* __restrict__ A,
    const float* __restrict__ W,
    const float* __restrict__ bias,
    float* __restrict__ C,
    int N, int K, int mode)
{
    __shared__ float As[8][132];   // padded: conflict-free transpose stores
    __shared__ float Bs[8][132];

    const int tid = threadIdx.x;
    const int m0 = blockIdx.y * 128;
    const int n0 = blockIdx.x * 128;

    // Global load mapping: each thread loads one float4 of A and one of W
    const int lr = tid >> 1;            // 0..127 (tile row)
    const int lc = (tid & 1) << 2;      // 0 or 4 (k offset)
    const float* Ap = A + (size_t)(m0 + lr) * K + lc;
    const float* Wp = W + (size_t)(n0 + lr) * K + lc;

    // Compute mapping: 16x16 thread grid, each 8x8 outputs
    const int tRow = (tid >> 4) << 3;   // m offset within tile
    const int tCol = (tid & 15) << 3;   // n offset within tile

    float acc[8][8];
#pragma unroll
    for (int i = 0; i < 8; ++i)
#pragma unroll
        for (int j = 0; j < 8; ++j) acc[i][j] = 0.0f;

    for (int k0 = 0; k0 < K; k0 += 8) {
        float4 av = *(const float4*)Ap;  Ap += 8;
        float4 wv = *(const float4*)Wp;  Wp += 8;
        __syncthreads();
        As[lc + 0][lr] = av.x; As[lc + 1][lr] = av.y;
        As[lc + 2][lr] = av.z; As[lc + 3][lr] = av.w;
        Bs[lc + 0][lr] = wv.x; Bs[lc + 1][lr] = wv.y;
        Bs[lc + 2][lr] = wv.z; Bs[lc + 3][lr] = wv.w;
        __syncthreads();
#pragma unroll
        for (int kk = 0; kk < 8; ++kk) {
            float a[8], b[8];
#pragma unroll
            for (int i = 0; i < 8; ++i) a[i] = As[kk][tRow + i];
#pragma unroll
            for (int j = 0; j < 8; ++j) b[j] = Bs[kk][tCol + j];
#pragma unroll
            for (int i = 0; i < 8; ++i)
#pragma unroll
                for (int j = 0; j < 8; ++j)
                    acc[i][j] = fmaf(a[i], b[j], acc[i][j]);
        }
    }

    // bias for this thread's 8 output columns
    float bv[8];
#pragma unroll
    for (int j = 0; j < 8; ++j) bv[j] = bias[n0 + tCol + j];

    if (mode == 0) {
#pragma unroll
        for (int i = 0; i < 8; ++i) {
            const int m = m0 + tRow + i;
            float4 v0, v1;
            v0.x = acc[i][0] + bv[0]; v0.y = acc[i][1] + bv[1];
            v0.z = acc[i][2] + bv[2]; v0.w = acc[i][3] + bv[3];
            v1.x = acc[i][4] + bv[4]; v1.y = acc[i][5] + bv[5];
            v1.z = acc[i][6] + bv[6]; v1.w = acc[i][7] + bv[7];
            float* cp = C + (size_t)m * N + n0 + tCol;
            *(float4*)(cp)     = v0;
            *(float4*)(cp + 4) = v1;
        }
    } else {
        // QKV scatter. Per-thread constants: n block fits within one (c,h,d0+8)
        const int n  = n0 + tCol;
        const int c  = n >> 10;           // 0=Q, 1=K, 2=V
        const int hh = (n >> 6) & (NHEADS - 1);
        const int d0 = n & (HDIM - 1);    // multiple of 8
        float* dst = (c == 0) ? g_Q : (c == 1) ? g_K : g_V;
#pragma unroll
        for (int i = 0; i < 8; ++i) {
            const int m = m0 + tRow + i;
            const int b = m >> 11;        // / SEQ
            const int t = m & (SEQ - 1);
            float* p = dst + ((size_t)((b * NHEADS + hh) * SEQ) + t) * HDIM + d0;
            float4 v0, v1;
            v0.x = acc[i][0] + bv[0]; v0.y = acc[i][1] + bv[1];
            v0.z = acc[i][2] + bv[2]; v0.w = acc[i][3] + bv[3];
            v1.x = acc[i][4] + bv[4]; v1.y = acc[i][5] + bv[5];
            v1.z = acc[i][6] + bv[6]; v1.w = acc[i][7] + bv[7];
            *(float4*)(p)     = v0;
            *(float4*)(p + 4) = v1;
        }
    }
}

// ---------------------------------------------------------------------------
// Sliding-window attention.
// Grid: (SEQ/64, NHEADS, BATCH). Block: 128 threads (4 warps).
// CTA handles 64 queries [q0, q0+63]; key window spans rows [q0, q0+127].
// K and V tiles (128 x 64 fp32 each) in 64 KB dynamic smem.
// One warp per query: lane l owns head dims l and l+32.
// ---------------------------------------------------------------------------
__global__ __launch_bounds__(128) void attn_kernel()
{
    extern __shared__ float sm[];
    float* Ks = sm;                 // [128][64]
    float* Vs = sm + 128 * HDIM;    // [128][64]

    const int q0 = blockIdx.x * 64;
    const int h  = blockIdx.y;
    const int b  = blockIdx.z;

    const size_t bh = (size_t)(b * NHEADS + h) * SEQ * HDIM;
    const float* Qg = g_Q + bh;
    const float* Kg = g_K + bh;
    const float* Vg = g_V + bh;

    const int tid = threadIdx.x;

    // Cooperative load: 128 rows x 64 cols = 2048 float4 per tensor
    for (int it = tid; it < 128 * 16; it += 128) {
        const int r  = it >> 4;          // smem row 0..127
        const int cv = (it & 15) << 2;   // float col 0..60
        const int jg = q0 + r;
        float4 kv, vv;
        if (jg < SEQ) {
            kv = *(const float4*)(Kg + (size_t)jg * HDIM + cv);
            vv = *(const float4*)(Vg + (size_t)jg * HDIM + cv);
        } else {
            kv = make_float4(0.f, 0.f, 0.f, 0.f);
            vv = kv;
        }
        *(float4*)(Ks + r * HDIM + cv) = kv;
        *(float4*)(Vs + r * HDIM + cv) = vv;
    }
    __syncthreads();

    const int w    = tid >> 5;
    const int lane = tid & 31;
    const unsigned FULL = 0xffffffffu;
    const float NEG_INF = -__int_as_float(0x7f800000);  // -inf

    for (int qq = 0; qq < 16; ++qq) {
        const int i_loc = w * 16 + qq;
        const int i     = q0 + i_loc;

        const float qA = Qg[(size_t)i * HDIM + lane];
        const float qB = Qg[(size_t)i * HDIM + lane + 32];
        const int nvalid = min(HALFWIN, SEQ - 1 - i);   // idx in [0, nvalid]

        // Scores: lane l holds s0 (idx=l), s1 (idx=l+32); lane 0 holds s2 (idx=64)
        float s0 = NEG_INF, s1 = NEG_INF, s2 = NEG_INF;
        for (int idx = 0; idx <= HALFWIN; ++idx) {
            const float* kr = Ks + (i_loc + idx) * HDIM;
            float part = qA * kr[lane] + qB * kr[lane + 32];
            part += __shfl_xor_sync(FULL, part, 16);
            part += __shfl_xor_sync(FULL, part, 8);
            part += __shfl_xor_sync(FULL, part, 4);
            part += __shfl_xor_sync(FULL, part, 2);
            part += __shfl_xor_sync(FULL, part, 1);
            float sc = part * 0.125f;                   // hd^-0.5
            if (idx > nvalid) sc = NEG_INF;
            if (idx < 32)      { if (lane == idx)      s0 = sc; }
            else if (idx < 64) { if (lane == idx - 32) s1 = sc; }
            else               { if (lane == 0)        s2 = sc; }
        }

        // Softmax over the (<=65) window
        float m = fmaxf(fmaxf(s0, s1), s2);
#pragma unroll
        for (int off = 16; off; off >>= 1)
            m = fmaxf(m, __shfl_xor_sync(FULL, m, off));

        const float p0 = __expf(s0 - m);
        const float p1 = __expf(s1 - m);
        const float p2 = __expf(s2 - m);
        float sum = p0 + p1 + p2;
#pragma unroll
        for (int off = 16; off; off >>= 1)
            sum += __shfl_xor_sync(FULL, sum, off);

        // O = P @ V
        float o0 = 0.f, o1 = 0.f;
#pragma unroll 4
        for (int idx = 0; idx < 32; ++idx) {
            const float pj = __shfl_sync(FULL, p0, idx);
            const float* vr = Vs + (i_loc + idx) * HDIM;
            o0 = fmaf(pj, vr[lane], o0);
            o1 = fmaf(pj, vr[lane + 32], o1);
        }
#pragma unroll 4
        for (int idx = 0; idx < 32; ++idx) {
            const float pj = __shfl_sync(FULL, p1, idx);
            const float* vr = Vs + (i_loc + 32 + idx) * HDIM;
            o0 = fmaf(pj, vr[lane], o0);
            o1 = fmaf(pj, vr[lane + 32], o1);
        }
        {
            const float pj = __shfl_sync(FULL, p2, 0);
            const float* vr = Vs + (i_loc + 64) * HDIM;
            o0 = fmaf(pj, vr[lane], o0);
            o1 = fmaf(pj, vr[lane + 32], o1);
        }

        const float inv = 1.0f / sum;
        float* op = g_attn + ((size_t)(b * SEQ + i)) * DMODEL + h * HDIM;
        op[lane]      = o0 * inv;
        op[lane + 32] = o1 * inv;
    }
}

// ---------------------------------------------------------------------------
extern "C" void kernel_launch(void* const* d_in, const int* in_sizes, int n_in,
                              void* d_out, int out_size)
{
    (void)in_sizes; (void)n_in; (void)out_size;
    const float* x      = (const float*)d_in[0];
    const float* w_qkv  = (const float*)d_in[1];
    const float* b_qkv  = (const float*)d_in[2];
    const float* w_out  = (const float*)d_in[3];
    const float* b_out  = (const float*)d_in[4];
    float* out = (float*)d_out;

    // Resolve scratch symbol + raise smem limit (host APIs, capture-safe, no allocs)
    void* attn_sym = nullptr;
    cudaGetSymbolAddress(&attn_sym, g_attn);
    cudaFuncSetAttribute(attn_kernel,
                         cudaFuncAttributeMaxDynamicSharedMemorySize, 65536);

    const int M = BATCH * SEQ;  // 4096

    // 1) QKV projection, scattered into g_Q/g_K/g_V [b,h,t,d]
    dim3 g1((3 * DMODEL) / 128, M / 128);
    sgemm_nt<<<g1, 256>>>(x, w_qkv, b_qkv, nullptr, 3 * DMODEL, DMODEL, 1);

    // 2) Windowed attention -> g_attn [b,t,h*64+d]
    dim3 g2(SEQ / 64, NHEADS, BATCH);
    attn_kernel<<<g2, 128, 65536>>>();

    // 3) Output projection -> d_out
    dim3 g3(DMODEL / 128, M / 128);
    sgemm_nt<<<g3, 256>>>((const float*)attn_sym, w_out, b_out, out,
                          DMODEL, DMODEL, 0);
}

// round 8
// speedup vs baseline: 1.1584x; 1.1584x over previous
#include <cuda_runtime.h>
#include <cuda_bf16.h>
#include <math.h>

// Problem constants
#define BATCH 2
#define SEQ   2048
#define DMODEL 1024
#define NHEADS 16
#define HDIM  64
#define HALFWIN 64          // keys j in [i, i+64]  (<=65 keys per query)

// Scratch (allocation-free rule: __device__ globals)
__device__ float g_Q[BATCH * NHEADS * SEQ * HDIM];     // [b,h,t,d]
__device__ float g_K[BATCH * NHEADS * SEQ * HDIM];
__device__ float g_V[BATCH * NHEADS * SEQ * HDIM];
__device__ float g_attn[BATCH * SEQ * DMODEL];         // [b,t,h*64+d]

// ---------------------------------------------------------------------------
// NT SGEMM: C[m,n] = sum_k A[m,k] * W[n,k] + bias[n]
// 128x128 tile, BK=8, 256 threads, 8x8 microtile.
// Double-buffered smem (1 barrier/k-tile), LDS.128 vector reads.
// mode 0: C row-major [M,N] (+bias); mode 1: QKV scatter into g_{Q,K,V}.
// ---------------------------------------------------------------------------
__global__ __launch_bounds__(256) void sgemm_nt(
    const float* __restrict__ A,
    const float* __restrict__ W,
    const float* __restrict__ bias,
    float* __restrict__ C,
    int N, int K, int mode)
{
    __shared__ float As[2][8][132];   // 132 pad: conflict-free transpose STS,
    __shared__ float Bs[2][8][132];   // rows stay 16B-aligned (132 % 4 == 0)

    const int tid = threadIdx.x;
    const int m0 = blockIdx.y * 128;
    const int n0 = blockIdx.x * 128;

    // Global load mapping: one float4 of A and one of W per thread per tile
    const int lr = tid >> 1;            // 0..127 (tile row)
    const int lc = (tid & 1) << 2;      // 0 or 4 (k offset)
    const float* Ap = A + (size_t)(m0 + lr) * K + lc;
    const float* Wp = W + (size_t)(n0 + lr) * K + lc;

    // Compute mapping: 16x16 thread grid, 8x8 outputs each
    const int tRow = (tid >> 4) << 3;
    const int tCol = (tid & 15) << 3;

    float acc[8][8];
#pragma unroll
    for (int i = 0; i < 8; ++i)
#pragma unroll
        for (int j = 0; j < 8; ++j) acc[i][j] = 0.0f;

    // Prologue: tile 0 -> buffer 0
    {
        float4 av = *(const float4*)Ap;  Ap += 8;
        float4 wv = *(const float4*)Wp;  Wp += 8;
        As[0][lc + 0][lr] = av.x; As[0][lc + 1][lr] = av.y;
        As[0][lc + 2][lr] = av.z; As[0][lc + 3][lr] = av.w;
        Bs[0][lc + 0][lr] = wv.x; Bs[0][lc + 1][lr] = wv.y;
        Bs[0][lc + 2][lr] = wv.z; Bs[0][lc + 3][lr] = wv.w;
    }
    __syncthreads();

    int buf = 0;
    for (int k0 = 8; k0 < K; k0 += 8) {
        // Prefetch next tile from gmem (overlaps with compute below)
        float4 av = *(const float4*)Ap;  Ap += 8;
        float4 wv = *(const float4*)Wp;  Wp += 8;

#pragma unroll
        for (int kk = 0; kk < 8; ++kk) {
            float4 a0 = *(const float4*)&As[buf][kk][tRow];
            float4 a1 = *(const float4*)&As[buf][kk][tRow + 4];
            float4 b0 = *(const float4*)&Bs[buf][kk][tCol];
            float4 b1 = *(const float4*)&Bs[buf][kk][tCol + 4];
            float a[8] = {a0.x, a0.y, a0.z, a0.w, a1.x, a1.y, a1.z, a1.w};
            float b[8] = {b0.x, b0.y, b0.z, b0.w, b1.x, b1.y, b1.z, b1.w};
#pragma unroll
            for (int i = 0; i < 8; ++i)
#pragma unroll
                for (int j = 0; j < 8; ++j)
                    acc[i][j] = fmaf(a[i], b[j], acc[i][j]);
        }

        const int nb = buf ^ 1;
        As[nb][lc + 0][lr] = av.x; As[nb][lc + 1][lr] = av.y;
        As[nb][lc + 2][lr] = av.z; As[nb][lc + 3][lr] = av.w;
        Bs[nb][lc + 0][lr] = wv.x; Bs[nb][lc + 1][lr] = wv.y;
        Bs[nb][lc + 2][lr] = wv.z; Bs[nb][lc + 3][lr] = wv.w;
        __syncthreads();
        buf = nb;
    }

    // Epilogue tile
#pragma unroll
    for (int kk = 0; kk < 8; ++kk) {
        float4 a0 = *(const float4*)&As[buf][kk][tRow];
        float4 a1 = *(const float4*)&As[buf][kk][tRow + 4];
        float4 b0 = *(const float4*)&Bs[buf][kk][tCol];
        float4 b1 = *(const float4*)&Bs[buf][kk][tCol + 4];
        float a[8] = {a0.x, a0.y, a0.z, a0.w, a1.x, a1.y, a1.z, a1.w};
        float b[8] = {b0.x, b0.y, b0.z, b0.w, b1.x, b1.y, b1.z, b1.w};
#pragma unroll
        for (int i = 0; i < 8; ++i)
#pragma unroll
            for (int j = 0; j < 8; ++j)
                acc[i][j] = fmaf(a[i], b[j], acc[i][j]);
    }

    float bv[8];
#pragma unroll
    for (int j = 0; j < 8; ++j) bv[j] = bias[n0 + tCol + j];

    if (mode == 0) {
#pragma unroll
        for (int i = 0; i < 8; ++i) {
            const int m = m0 + tRow + i;
            float4 v0, v1;
            v0.x = acc[i][0] + bv[0]; v0.y = acc[i][1] + bv[1];
            v0.z = acc[i][2] + bv[2]; v0.w = acc[i][3] + bv[3];
            v1.x = acc[i][4] + bv[4]; v1.y = acc[i][5] + bv[5];
            v1.z = acc[i][6] + bv[6]; v1.w = acc[i][7] + bv[7];
            float* cp = C + (size_t)m * N + n0 + tCol;
            *(float4*)(cp)     = v0;
            *(float4*)(cp + 4) = v1;
        }
    } else {
        const int n  = n0 + tCol;
        const int c  = n >> 10;           // 0=Q, 1=K, 2=V
        const int hh = (n >> 6) & (NHEADS - 1);
        const int d0 = n & (HDIM - 1);
        float* dst = (c == 0) ? g_Q : (c == 1) ? g_K : g_V;
#pragma unroll
        for (int i = 0; i < 8; ++i) {
            const int m = m0 + tRow + i;
            const int b = m >> 11;
            const int t = m & (SEQ - 1);
            float* p = dst + ((size_t)((b * NHEADS + hh) * SEQ) + t) * HDIM + d0;
            float4 v0, v1;
            v0.x = acc[i][0] + bv[0]; v0.y = acc[i][1] + bv[1];
            v0.z = acc[i][2] + bv[2]; v0.w = acc[i][3] + bv[3];
            v1.x = acc[i][4] + bv[4]; v1.y = acc[i][5] + bv[5];
            v1.z = acc[i][6] + bv[6]; v1.w = acc[i][7] + bv[7];
            *(float4*)(p)     = v0;
            *(float4*)(p + 4) = v1;
        }
    }
}

// ---------------------------------------------------------------------------
// Sliding-window attention, lane-per-key layout (no shuffles in hot loops).
// Grid: (SEQ/64, NHEADS, BATCH). Block: 128 threads (4 warps).
// CTA: 64 queries; key window rows [q0, q0+127] staged in smem.
// Row pad = 68 floats: lane-per-key LDS.128 is bank-conflict-free
// (8-lane phase stride 272 B ≡ 16 B mod 128 -> distinct banks).
// ---------------------------------------------------------------------------
#define KPAD 68
#define PSTR 72

__global__ __launch_bounds__(128) void attn_kernel()
{
    extern __shared__ float sm[];
    float* Qs = sm;                      // [64][KPAD]
    float* Ks = sm + 64 * KPAD;          // [128][KPAD]
    float* Vs = sm + (64 + 128) * KPAD;  // [128][KPAD]
    float* Ps = sm + (64 + 256) * KPAD;  // [4][PSTR] per-warp probabilities

    const int q0 = blockIdx.x * 64;
    const int h  = blockIdx.y;
    const int b  = blockIdx.z;

    const size_t bh = (size_t)(b * NHEADS + h) * SEQ * HDIM;
    const float* Qg = g_Q + bh;
    const float* Kg = g_K + bh;
    const float* Vg = g_V + bh;

    const int tid = threadIdx.x;

    // Stage Q tile (64 rows, always in range)
    for (int it = tid; it < 64 * 16; it += 128) {
        const int r  = it >> 4;
        const int cv = (it & 15) << 2;
        float4 qv = *(const float4*)(Qg + (size_t)(q0 + r) * HDIM + cv);
        *(float4*)(Qs + r * KPAD + cv) = qv;
    }
    // Stage K and V tiles (128 rows, zero-pad past SEQ)
    for (int it = tid; it < 128 * 16; it += 128) {
        const int r  = it >> 4;
        const int cv = (it & 15) << 2;
        const int jg = q0 + r;
        float4 kv, vv;
        if (jg < SEQ) {
            kv = *(const float4*)(Kg + (size_t)jg * HDIM + cv);
            vv = *(const float4*)(Vg + (size_t)jg * HDIM + cv);
        } else {
            kv = make_float4(0.f, 0.f, 0.f, 0.f);
            vv = kv;
        }
        *(float4*)(Ks + r * KPAD + cv) = kv;
        *(float4*)(Vs + r * KPAD + cv) = vv;
    }
    __syncthreads();

    const int w    = tid >> 5;
    const int lane = tid & 31;
    const unsigned FULL = 0xffffffffu;
    const float NEG_INF = -__int_as_float(0x7f800000);
    float* pw = Ps + w * PSTR;

    for (int qq = 0; qq < 16; ++qq) {
        const int i_loc = w * 16 + qq;
        const int i     = q0 + i_loc;
        const int nvalid = min(HALFWIN, SEQ - 1 - i);   // valid idx: [0, nvalid]
        const float* qr = Qs + i_loc * KPAD;

        // --- QK^T: lane handles keys idx = c*32 + lane ---
        float s[3];
#pragma unroll
        for (int c = 0; c < 3; ++c) {
            const int idx = c * 32 + lane;
            const int row = min(i_loc + idx, 127);      // clamp (masked anyway)
            const float* kr = Ks + row * KPAD;
            float acc = 0.0f;
#pragma unroll
            for (int d4 = 0; d4 < 16; ++d4) {
                float4 k4 = *(const float4*)(kr + (d4 << 2));
                float4 q4 = *(const float4*)(qr + (d4 << 2));  // broadcast
                acc = fmaf(q4.x, k4.x, acc);
                acc = fmaf(q4.y, k4.y, acc);
                acc = fmaf(q4.z, k4.z, acc);
                acc = fmaf(q4.w, k4.w, acc);
            }
            float sc = acc * 0.125f;                    // hd^-0.5
            s[c] = (idx > nvalid) ? NEG_INF : sc;
        }

        // --- softmax over <=65 scores ---
        float m = fmaxf(fmaxf(s[0], s[1]), s[2]);
#pragma unroll
        for (int off = 16; off; off >>= 1)
            m = fmaxf(m, __shfl_xor_sync(FULL, m, off));
        const float p0 = __expf(s[0] - m);
        const float p1 = __expf(s[1] - m);
        const float p2 = __expf(s[2] - m);
        float sum = p0 + p1 + p2;
#pragma unroll
        for (int off = 16; off; off >>= 1)
            sum += __shfl_xor_sync(FULL, sum, off);
        const float inv = 1.0f / sum;

        __syncwarp();                 // protect Ps from previous query's reads
        pw[lane]      = p0 * inv;
        pw[lane + 32] = p1 * inv;
        if (lane == 0) pw[64] = p2 * inv;
        __syncwarp();

        // --- O = P @ V: lane owns dims (lane, lane+32) ---
        float o0 = 0.f, o1 = 0.f;
        const float* vbase = Vs + i_loc * KPAD;
#pragma unroll 8
        for (int j = 0; j < 64; ++j) {
            const float pj = pw[j];                     // broadcast
            const float* vr = vbase + j * KPAD;
            o0 = fmaf(pj, vr[lane], o0);
            o1 = fmaf(pj, vr[lane + 32], o1);
        }
        {
            const float pj = pw[64];
            const float* vr = vbase + 64 * KPAD;
            o0 = fmaf(pj, vr[lane], o0);
            o1 = fmaf(pj, vr[lane + 32], o1);
        }

        float* op = g_attn + ((size_t)(b * SEQ + i)) * DMODEL + h * HDIM;
        op[lane]      = o0;
        op[lane + 32] = o1;
    }
}

// ---------------------------------------------------------------------------
extern "C" void kernel_launch(void* const* d_in, const int* in_sizes, int n_in,
                              void* d_out, int out_size)
{
    (void)in_sizes; (void)n_in; (void)out_size;
    const float* x      = (const float*)d_in[0];
    const float* w_qkv  = (const float*)d_in[1];
    const float* b_qkv  = (const float*)d_in[2];
    const float* w_out  = (const float*)d_in[3];
    const float* b_out  = (const float*)d_in[4];
    float* out = (float*)d_out;

    void* attn_sym = nullptr;
    cudaGetSymbolAddress(&attn_sym, g_attn);

    const int ATTN_SMEM = (64 + 128 + 128) * KPAD * 4 + 4 * PSTR * 4;  // ~88.6 KB
    cudaFuncSetAttribute(attn_kernel,
                         cudaFuncAttributeMaxDynamicSharedMemorySize, ATTN_SMEM);

    const int M = BATCH * SEQ;  // 4096

    // 1) QKV projection -> g_Q/g_K/g_V [b,h,t,d]
    dim3 g1((3 * DMODEL) / 128, M / 128);
    sgemm_nt<<<g1, 256>>>(x, w_qkv, b_qkv, nullptr, 3 * DMODEL, DMODEL, 1);

    // 2) Windowed attention -> g_attn [b,t,h*64+d]
    dim3 g2(SEQ / 64, NHEADS, BATCH);
    attn_kernel<<<g2, 128, ATTN_SMEM>>>();

    // 3) Output projection -> d_out
    dim3 g3(DMODEL / 128, M / 128);
    sgemm_nt<<<g3, 256>>>((const float*)attn_sym, w_out, b_out, out,
                          DMODEL, DMODEL, 0);
}

// round 9
// speedup vs baseline: 1.1626x; 1.0036x over previous
#include <cuda_runtime.h>
#include <cuda_bf16.h>
#include <math.h>

// Problem constants
#define BATCH 2
#define SEQ   2048
#define DMODEL 1024
#define NHEADS 16
#define HDIM  64
#define HALFWIN 64          // keys j in [i, i+64]  (<=65 keys per query)

// Scratch (allocation-free rule: __device__ globals)
__device__ float g_Q[BATCH * NHEADS * SEQ * HDIM];     // [b,h,t,d]
__device__ float g_K[BATCH * NHEADS * SEQ * HDIM];
__device__ float g_V[BATCH * NHEADS * SEQ * HDIM];
__device__ float g_attn[BATCH * SEQ * DMODEL];         // [b,t,h*64+d]

// ---- packed f32x2 helpers (Blackwell FFMA2 path; ptxas never emits it) ----
__device__ __forceinline__ unsigned long long pack2(float lo, float hi) {
    unsigned long long r;
    asm("mov.b64 %0, {%1, %2};" : "=l"(r) : "f"(lo), "f"(hi));
    return r;
}
__device__ __forceinline__ void unpack2(unsigned long long v, float& lo, float& hi) {
    asm("mov.b64 {%0, %1}, %2;" : "=f"(lo), "=f"(hi) : "l"(v));
}
__device__ __forceinline__ void fma2(unsigned long long& d,
                                     unsigned long long a, unsigned long long b) {
    asm("fma.rn.f32x2 %0, %1, %2, %0;" : "+l"(d) : "l"(a), "l"(b));
}
__device__ __forceinline__ void add2(unsigned long long& d, unsigned long long a) {
    asm("add.rn.f32x2 %0, %0, %1;" : "+l"(d) : "l"(a));
}

// ---------------------------------------------------------------------------
// NT SGEMM: C[m,n] = sum_k A[m,k] * W[n,k] + bias[n]
// 128x128 tile, BK=8, 256 threads, 8x8 microtile held as 8x4 packed f32x2.
// Double-buffered smem, LDS.128 reads, fma.rn.f32x2 inner product.
// mode 0: C row-major [M,N] (+bias); mode 1: QKV scatter into g_{Q,K,V}.
// ---------------------------------------------------------------------------
__global__ __launch_bounds__(256) void sgemm_nt(
    const float* __restrict__ A,
    const float* __restrict__ W,
    const float* __restrict__ bias,
    float* __restrict__ C,
    int N, int K, int mode)
{
    __shared__ float As[2][8][132];   // 132 pad: conflict-free transpose STS;
    __shared__ float Bs[2][8][132];   // row starts stay 16B-aligned (132*4=528=33*16)

    const int tid = threadIdx.x;
    const int m0 = blockIdx.y * 128;
    const int n0 = blockIdx.x * 128;

    const int lr = tid >> 1;            // 0..127 (tile row)
    const int lc = (tid & 1) << 2;      // 0 or 4 (k offset)
    const float* Ap = A + (size_t)(m0 + lr) * K + lc;
    const float* Wp = W + (size_t)(n0 + lr) * K + lc;

    const int tRow = (tid >> 4) << 3;
    const int tCol = (tid & 15) << 3;

    unsigned long long accP[8][4];      // accP[i][j2] = (acc[i][2j2], acc[i][2j2+1])
#pragma unroll
    for (int i = 0; i < 8; ++i)
#pragma unroll
        for (int j = 0; j < 4; ++j) accP[i][j] = 0ULL;   // packed +0.0f pair

    // Prologue: tile 0 -> buffer 0
    {
        float4 av = *(const float4*)Ap;  Ap += 8;
        float4 wv = *(const float4*)Wp;  Wp += 8;
        As[0][lc + 0][lr] = av.x; As[0][lc + 1][lr] = av.y;
        As[0][lc + 2][lr] = av.z; As[0][lc + 3][lr] = av.w;
        Bs[0][lc + 0][lr] = wv.x; Bs[0][lc + 1][lr] = wv.y;
        Bs[0][lc + 2][lr] = wv.z; Bs[0][lc + 3][lr] = wv.w;
    }
    __syncthreads();

    int buf = 0;
    for (int k0 = 8; k0 < K; k0 += 8) {
        float4 av = *(const float4*)Ap;  Ap += 8;       // prefetch next tile
        float4 wv = *(const float4*)Wp;  Wp += 8;

#pragma unroll
        for (int kk = 0; kk < 8; ++kk) {
            float4 a0 = *(const float4*)&As[buf][kk][tRow];
            float4 a1 = *(const float4*)&As[buf][kk][tRow + 4];
            ulonglong2 bq0 = *(const ulonglong2*)&Bs[buf][kk][tCol];      // (b0,b1),(b2,b3)
            ulonglong2 bq1 = *(const ulonglong2*)&Bs[buf][kk][tCol + 4];  // (b4,b5),(b6,b7)
            float a[8] = {a0.x, a0.y, a0.z, a0.w, a1.x, a1.y, a1.z, a1.w};
            unsigned long long bP[4] = {bq0.x, bq0.y, bq1.x, bq1.y};
#pragma unroll
            for (int i = 0; i < 8; ++i) {
                unsigned long long aP = pack2(a[i], a[i]);
#pragma unroll
                for (int j = 0; j < 4; ++j)
                    fma2(accP[i][j], aP, bP[j]);
            }
        }

        const int nb = buf ^ 1;
        As[nb][lc + 0][lr] = av.x; As[nb][lc + 1][lr] = av.y;
        As[nb][lc + 2][lr] = av.z; As[nb][lc + 3][lr] = av.w;
        Bs[nb][lc + 0][lr] = wv.x; Bs[nb][lc + 1][lr] = wv.y;
        Bs[nb][lc + 2][lr] = wv.z; Bs[nb][lc + 3][lr] = wv.w;
        __syncthreads();
        buf = nb;
    }

    // Epilogue tile
#pragma unroll
    for (int kk = 0; kk < 8; ++kk) {
        float4 a0 = *(const float4*)&As[buf][kk][tRow];
        float4 a1 = *(const float4*)&As[buf][kk][tRow + 4];
        ulonglong2 bq0 = *(const ulonglong2*)&Bs[buf][kk][tCol];
        ulonglong2 bq1 = *(const ulonglong2*)&Bs[buf][kk][tCol + 4];
        float a[8] = {a0.x, a0.y, a0.z, a0.w, a1.x, a1.y, a1.z, a1.w};
        unsigned long long bP[4] = {bq0.x, bq0.y, bq1.x, bq1.y};
#pragma unroll
        for (int i = 0; i < 8; ++i) {
            unsigned long long aP = pack2(a[i], a[i]);
#pragma unroll
            for (int j = 0; j < 4; ++j)
                fma2(accP[i][j], aP, bP[j]);
        }
    }

    // bias (packed pairs; bias + n0 + tCol is 32B-aligned)
    {
        const unsigned long long* bp = (const unsigned long long*)(bias + n0 + tCol);
        unsigned long long bvP[4] = {bp[0], bp[1], bp[2], bp[3]};
#pragma unroll
        for (int i = 0; i < 8; ++i)
#pragma unroll
            for (int j = 0; j < 4; ++j)
                add2(accP[i][j], bvP[j]);
    }

    if (mode == 0) {
#pragma unroll
        for (int i = 0; i < 8; ++i) {
            const int m = m0 + tRow + i;
            float4 v0, v1;
            unpack2(accP[i][0], v0.x, v0.y);
            unpack2(accP[i][1], v0.z, v0.w);
            unpack2(accP[i][2], v1.x, v1.y);
            unpack2(accP[i][3], v1.z, v1.w);
            float* cp = C + (size_t)m * N + n0 + tCol;
            *(float4*)(cp)     = v0;
            *(float4*)(cp + 4) = v1;
        }
    } else {
        const int n  = n0 + tCol;
        const int c  = n >> 10;           // 0=Q, 1=K, 2=V
        const int hh = (n >> 6) & (NHEADS - 1);
        const int d0 = n & (HDIM - 1);
        float* dst = (c == 0) ? g_Q : (c == 1) ? g_K : g_V;
#pragma unroll
        for (int i = 0; i < 8; ++i) {
            const int m = m0 + tRow + i;
            const int b = m >> 11;
            const int t = m & (SEQ - 1);
            float* p = dst + ((size_t)((b * NHEADS + hh) * SEQ) + t) * HDIM + d0;
            float4 v0, v1;
            unpack2(accP[i][0], v0.x, v0.y);
            unpack2(accP[i][1], v0.z, v0.w);
            unpack2(accP[i][2], v1.x, v1.y);
            unpack2(accP[i][3], v1.z, v1.w);
            *(float4*)(p)     = v0;
            *(float4*)(p + 4) = v1;
        }
    }
}

// ---------------------------------------------------------------------------
// Sliding-window attention, lane-per-key QK + packed-f32x2 PV.
// Grid: (SEQ/64, NHEADS, BATCH). Block: 128 threads (4 warps).
// KPAD=68: lane-per-key vector loads bank-conflict-free (272 B ≡ 16 mod 128).
// ---------------------------------------------------------------------------
#define KPAD 68
#define P64  66   // u64 slots per warp in Ps

__global__ __launch_bounds__(128) void attn_kernel()
{
    extern __shared__ float sm[];
    float* Qs = sm;                      // [64][KPAD]
    float* Ks = sm + 64 * KPAD;          // [128][KPAD]
    float* Vs = sm + (64 + 128) * KPAD;  // [128][KPAD]
    unsigned long long* Ps =             // [4][P64] packed (p,p) per key
        (unsigned long long*)(sm + (64 + 256) * KPAD);

    const int q0 = blockIdx.x * 64;
    const int h  = blockIdx.y;
    const int b  = blockIdx.z;

    const size_t bh = (size_t)(b * NHEADS + h) * SEQ * HDIM;
    const float* Qg = g_Q + bh;
    const float* Kg = g_K + bh;
    const float* Vg = g_V + bh;

    const int tid = threadIdx.x;

    for (int it = tid; it < 64 * 16; it += 128) {
        const int r  = it >> 4;
        const int cv = (it & 15) << 2;
        float4 qv = *(const float4*)(Qg + (size_t)(q0 + r) * HDIM + cv);
        *(float4*)(Qs + r * KPAD + cv) = qv;
    }
    for (int it = tid; it < 128 * 16; it += 128) {
        const int r  = it >> 4;
        const int cv = (it & 15) << 2;
        const int jg = q0 + r;
        float4 kv, vv;
        if (jg < SEQ) {
            kv = *(const float4*)(Kg + (size_t)jg * HDIM + cv);
            vv = *(const float4*)(Vg + (size_t)jg * HDIM + cv);
        } else {
            kv = make_float4(0.f, 0.f, 0.f, 0.f);
            vv = kv;
        }
        *(float4*)(Ks + r * KPAD + cv) = kv;
        *(float4*)(Vs + r * KPAD + cv) = vv;
    }
    __syncthreads();

    const int w    = tid >> 5;
    const int lane = tid & 31;
    const unsigned FULL = 0xffffffffu;
    const float NEG_INF = -__int_as_float(0x7f800000);
    unsigned long long* pw = Ps + w * P64;

    for (int qq = 0; qq < 16; ++qq) {
        const int i_loc = w * 16 + qq;
        const int i     = q0 + i_loc;
        const int nvalid = min(HALFWIN, SEQ - 1 - i);
        const ulonglong2* qp = (const ulonglong2*)(Qs + i_loc * KPAD);

        // --- QK^T: lane handles keys idx = c*32 + lane; packed dot ---
        float s[3];
#pragma unroll
        for (int c = 0; c < 3; ++c) {
            const int idx = c * 32 + lane;
            const int row = min(i_loc + idx, 127);
            const ulonglong2* kp = (const ulonglong2*)(Ks + row * KPAD);
            unsigned long long acc2 = 0ULL;
#pragma unroll
            for (int d8 = 0; d8 < 16; ++d8) {      // 16 x 4 floats = 64 dims
                ulonglong2 kq = kp[d8];
                ulonglong2 qd = qp[d8];
                fma2(acc2, qd.x, kq.x);
                fma2(acc2, qd.y, kq.y);
            }
            float alo, ahi;
            unpack2(acc2, alo, ahi);
            float sc = (alo + ahi) * 0.125f;        // hd^-0.5
            s[c] = (idx > nvalid) ? NEG_INF : sc;
        }

        // --- softmax over <=65 scores ---
        float m = fmaxf(fmaxf(s[0], s[1]), s[2]);
#pragma unroll
        for (int off = 16; off; off >>= 1)
            m = fmaxf(m, __shfl_xor_sync(FULL, m, off));
        const float p0 = __expf(s[0] - m);
        const float p1 = __expf(s[1] - m);
        const float p2 = __expf(s[2] - m);
        float sum = p0 + p1 + p2;
#pragma unroll
        for (int off = 16; off; off >>= 1)
            sum += __shfl_xor_sync(FULL, sum, off);
        const float inv = 1.0f / sum;

        __syncwarp();
        {
            const float P0 = p0 * inv, P1 = p1 * inv;
            pw[lane]      = pack2(P0, P0);
            pw[lane + 32] = pack2(P1, P1);
            if (lane == 0) { const float P2 = p2 * inv; pw[64] = pack2(P2, P2); }
        }
        __syncwarp();

        // --- O = P @ V: lane owns dims (2*lane, 2*lane+1), packed FMA ---
        unsigned long long o2 = 0ULL;
        const float* vbase = Vs + i_loc * KPAD + 2 * lane;
#pragma unroll 8
        for (int j = 0; j < 64; ++j) {
            unsigned long long v2 = *(const unsigned long long*)(vbase + j * KPAD);
            fma2(o2, pw[j], v2);
        }
        {
            unsigned long long v2 = *(const unsigned long long*)(vbase + 64 * KPAD);
            fma2(o2, pw[64], v2);
        }

        float* op = g_attn + ((size_t)(b * SEQ + i)) * DMODEL + h * HDIM;
        *(unsigned long long*)(op + 2 * lane) = o2;   // 8B-aligned packed store
    }
}

// ---------------------------------------------------------------------------
extern "C" void kernel_launch(void* const* d_in, const int* in_sizes, int n_in,
                              void* d_out, int out_size)
{
    (void)in_sizes; (void)n_in; (void)out_size;
    const float* x      = (const float*)d_in[0];
    const float* w_qkv  = (const float*)d_in[1];
    const float* b_qkv  = (const float*)d_in[2];
    const float* w_out  = (const float*)d_in[3];
    const float* b_out  = (const float*)d_in[4];
    float* out = (float*)d_out;

    void* attn_sym = nullptr;
    cudaGetSymbolAddress(&attn_sym, g_attn);

    const int ATTN_SMEM = (64 + 128 + 128) * KPAD * 4 + 4 * P64 * 8;  // ~89.2 KB
    cudaFuncSetAttribute(attn_kernel,
                         cudaFuncAttributeMaxDynamicSharedMemorySize, ATTN_SMEM);

    const int M = BATCH * SEQ;  // 4096

    // 1) QKV projection -> g_Q/g_K/g_V [b,h,t,d]
    dim3 g1((3 * DMODEL) / 128, M / 128);
    sgemm_nt<<<g1, 256>>>(x, w_qkv, b_qkv, nullptr, 3 * DMODEL, DMODEL, 1);

    // 2) Windowed attention -> g_attn [b,t,h*64+d]
    dim3 g2(SEQ / 64, NHEADS, BATCH);
    attn_kernel<<<g2, 128, ATTN_SMEM>>>();

    // 3) Output projection -> d_out
    dim3 g3(DMODEL / 128, M / 128);
    sgemm_nt<<<g3, 256>>>((const float*)attn_sym, w_out, b_out, out,
                          DMODEL, DMODEL, 0);
}

// round 10
// speedup vs baseline: 1.9887x; 1.7106x over previous
#include <cuda_runtime.h>
#include <cuda_bf16.h>
#include <math.h>

// Problem constants
#define BATCH 2
#define SEQ   2048
#define DMODEL 1024
#define NHEADS 16
#define HDIM  64
#define HALFWIN 64          // keys j in [i, i+64]  (<=65 keys per query)

// Scratch (allocation-free rule: __device__ globals)
__device__ float g_Q[BATCH * NHEADS * SEQ * HDIM];     // [b,h,t,d]
__device__ float g_K[BATCH * NHEADS * SEQ * HDIM];
__device__ float g_V[BATCH * NHEADS * SEQ * HDIM];
__device__ float g_attn[BATCH * SEQ * DMODEL];         // [b,t,h*64+d]

// ---- packed f32x2 helpers (used by attention kernel) ----
__device__ __forceinline__ unsigned long long pack2(float lo, float hi) {
    unsigned long long r;
    asm("mov.b64 %0, {%1, %2};" : "=l"(r) : "f"(lo), "f"(hi));
    return r;
}
__device__ __forceinline__ void unpack2(unsigned long long v, float& lo, float& hi) {
    asm("mov.b64 {%0, %1}, %2;" : "=f"(lo), "=f"(hi) : "l"(v));
}
__device__ __forceinline__ void fma2(unsigned long long& d,
                                     unsigned long long a, unsigned long long b) {
    asm("fma.rn.f32x2 %0, %1, %2, %0;" : "+l"(d) : "l"(a), "l"(b));
}

// ---- bf16 split helpers ----
__device__ __forceinline__ void split2(float f0, float f1,
                                       unsigned& hi, unsigned& lo) {
    __nv_bfloat16 h0 = __float2bfloat16_rn(f0);
    __nv_bfloat16 h1 = __float2bfloat16_rn(f1);
    float r0 = f0 - __bfloat162float(h0);
    float r1 = f1 - __bfloat162float(h1);
    __nv_bfloat16 l0 = __float2bfloat16_rn(r0);
    __nv_bfloat16 l1 = __float2bfloat16_rn(r1);
    __nv_bfloat162 hp = __halves2bfloat162(h0, h1);   // x=low 16b = k-even elem
    __nv_bfloat162 lp = __halves2bfloat162(l0, l1);
    hi = *reinterpret_cast<unsigned*>(&hp);
    lo = *reinterpret_cast<unsigned*>(&lp);
}

__device__ __forceinline__ void mma_bf16(float* d,
    unsigned a0, unsigned a1, unsigned a2, unsigned a3,
    unsigned b0, unsigned b1)
{
    asm("mma.sync.aligned.m16n8k16.row.col.f32.bf16.bf16.f32 "
        "{%0,%1,%2,%3}, {%4,%5,%6,%7}, {%8,%9}, {%0,%1,%2,%3};"
        : "+f"(d[0]), "+f"(d[1]), "+f"(d[2]), "+f"(d[3])
        : "r"(a0), "r"(a1), "r"(a2), "r"(a3), "r"(b0), "r"(b1));
}

// ---------------------------------------------------------------------------
// NT GEMM, bf16x3 split on tensor cores: C[m,n] = sum_k A[m,k]*W[n,k] + bias[n]
// A [M,K] row-major, W [N,K] row-major (= B col-major for mma row.col).
// CTA 128x128, BK=32, 256 threads = 8 warps (2m x 4n grid, 64x32 warp tiles).
// Smem holds pre-split packed-bf16x2 tiles (hi/lo for A and W), double-buffered.
// PSTR=20 u32 row stride: fragment LDS pattern (20g + t4) mod 32 all-distinct.
// mode 0: C row-major (+bias); mode 1: QKV scatter into g_{Q,K,V} (+bias).
// ---------------------------------------------------------------------------
#define PSTR 20
#define TILE_U32 (128 * PSTR)          // 2560 u32 per tile per buffer

__global__ __launch_bounds__(256) void gemm_bf16x3(
    const float* __restrict__ A,
    const float* __restrict__ W,
    const float* __restrict__ bias,
    float* __restrict__ C,
    int N, int K, int mode)
{
    extern __shared__ unsigned smem_u[];
    unsigned* sAhi = smem_u;                    // [2][TILE_U32]
    unsigned* sAlo = sAhi + 2 * TILE_U32;
    unsigned* sWhi = sAlo + 2 * TILE_U32;
    unsigned* sWlo = sWhi + 2 * TILE_U32;

    const int tid = threadIdx.x;
    const int m0 = blockIdx.y * 128;
    const int n0 = blockIdx.x * 128;

    // Staging map: thread -> (row 0..127, 16-float column half)
    const int srow = tid >> 1;
    const int scol = (tid & 1) << 4;            // float col base (0 or 16)
    const float* Ap = A + (size_t)(m0 + srow) * K + scol;
    const float* Wp = W + (size_t)(n0 + srow) * K + scol;

    const int wid  = tid >> 5;
    const int lane = tid & 31;
    const int wm = wid >> 2, wn = wid & 3;      // 2 x 4 warp grid
    const int mbase = wm * 64, nbase = wn * 32;
    const int g  = lane >> 2;                   // 0..7
    const int t4 = lane & 3;                    // 0..3

    float acc[4][4][4];
#pragma unroll
    for (int mt = 0; mt < 4; ++mt)
#pragma unroll
        for (int nt = 0; nt < 4; ++nt)
#pragma unroll
            for (int r = 0; r < 4; ++r) acc[mt][nt][r] = 0.0f;

    float4 fa[4], fw[4];

#define LOAD_STAGE()  do {                                        \
        fa[0] = *(const float4*)(Ap +  0);                        \
        fa[1] = *(const float4*)(Ap +  4);                        \
        fa[2] = *(const float4*)(Ap +  8);                        \
        fa[3] = *(const float4*)(Ap + 12);                        \
        fw[0] = *(const float4*)(Wp +  0);                        \
        fw[1] = *(const float4*)(Wp +  4);                        \
        fw[2] = *(const float4*)(Wp +  8);                        \
        fw[3] = *(const float4*)(Wp + 12);                        \
        Ap += 32;  Wp += 32;  } while (0)

#define STORE_STAGE(buf)  do {                                    \
        const int base = (buf) * TILE_U32 + srow * PSTR + (scol >> 1); \
        unsigned h, l;                                            \
        _Pragma("unroll")                                         \
        for (int i = 0; i < 4; ++i) {                             \
            split2(fa[i].x, fa[i].y, h, l);                       \
            sAhi[base + 2*i]     = h;  sAlo[base + 2*i]     = l;  \
            split2(fa[i].z, fa[i].w, h, l);                       \
            sAhi[base + 2*i + 1] = h;  sAlo[base + 2*i + 1] = l;  \
            split2(fw[i].x, fw[i].y, h, l);                       \
            sWhi[base + 2*i]     = h;  sWlo[base + 2*i]     = l;  \
            split2(fw[i].z, fw[i].w, h, l);                       \
            sWhi[base + 2*i + 1] = h;  sWlo[base + 2*i + 1] = l;  \
        } } while (0)

#define COMPUTE(buf)  do {                                        \
        const unsigned* bAh = sAhi + (buf) * TILE_U32;            \
        const unsigned* bAl = sAlo + (buf) * TILE_U32;            \
        const unsigned* bWh = sWhi + (buf) * TILE_U32;            \
        const unsigned* bWl = sWlo + (buf) * TILE_U32;            \
        _Pragma("unroll")                                         \
        for (int s = 0; s < 2; ++s) {                             \
            const int cs = s * 8 + t4;                            \
            unsigned bh0[4], bh1[4], bl0[4], bl1[4];              \
            _Pragma("unroll")                                     \
            for (int nt = 0; nt < 4; ++nt) {                      \
                const int rb = (nbase + nt * 8 + g) * PSTR + cs;  \
                bh0[nt] = bWh[rb];     bh1[nt] = bWh[rb + 4];     \
                bl0[nt] = bWl[rb];     bl1[nt] = bWl[rb + 4];     \
            }                                                     \
            _Pragma("unroll")                                     \
            for (int mt = 0; mt < 4; ++mt) {                      \
                const int r0 = (mbase + mt * 16 + g) * PSTR + cs; \
                const int r1 = r0 + 8 * PSTR;                     \
                unsigned ah0 = bAh[r0],   ah1 = bAh[r1];          \
                unsigned ah2 = bAh[r0+4], ah3 = bAh[r1+4];        \
                unsigned al0 = bAl[r0],   al1 = bAl[r1];          \
                unsigned al2 = bAl[r0+4], al3 = bAl[r1+4];        \
                _Pragma("unroll")                                 \
                for (int nt = 0; nt < 4; ++nt) {                  \
                    mma_bf16(acc[mt][nt], ah0,ah1,ah2,ah3, bh0[nt], bh1[nt]); \
                    mma_bf16(acc[mt][nt], ah0,ah1,ah2,ah3, bl0[nt], bl1[nt]); \
                    mma_bf16(acc[mt][nt], al0,al1,al2,al3, bh0[nt], bh1[nt]); \
                } } } } while (0)

    // Prologue
    LOAD_STAGE();
    STORE_STAGE(0);
    __syncthreads();

    int buf = 0;
    for (int k0 = 32; k0 < K; k0 += 32) {
        LOAD_STAGE();
        COMPUTE(buf);
        STORE_STAGE(buf ^ 1);
        __syncthreads();
        buf ^= 1;
    }
    COMPUTE(buf);

    // ---- epilogue ----
    if (mode == 0) {
#pragma unroll
        for (int mt = 0; mt < 4; ++mt)
#pragma unroll
            for (int nt = 0; nt < 4; ++nt) {
                const int row0 = m0 + mbase + mt * 16 + g;
                const int col  = n0 + nbase + nt * 8 + 2 * t4;
                const float b0v = bias[col], b1v = bias[col + 1];
                float2 v;
                v.x = acc[mt][nt][0] + b0v; v.y = acc[mt][nt][1] + b1v;
                *(float2*)(C + (size_t)row0 * N + col) = v;
                v.x = acc[mt][nt][2] + b0v; v.y = acc[mt][nt][3] + b1v;
                *(float2*)(C + (size_t)(row0 + 8) * N + col) = v;
            }
    } else {
        const int cgrp = n0 >> 10;                 // 0=Q,1=K,2=V (CTA-constant)
        float* dst = (cgrp == 0) ? g_Q : (cgrp == 1) ? g_K : g_V;
        const int bb = m0 >> 11;                   // batch (CTA-constant)
#pragma unroll
        for (int mt = 0; mt < 4; ++mt)
#pragma unroll
            for (int nt = 0; nt < 4; ++nt) {
                const int col = n0 + nbase + nt * 8 + 2 * t4;
                const int hh  = (col >> 6) & (NHEADS - 1);
                const int d0  = col & (HDIM - 1);
                const float b0v = bias[col], b1v = bias[col + 1];
                const int row0 = m0 + mbase + mt * 16 + g;
                const int t0   = row0 & (SEQ - 1);
                float* p = dst + ((size_t)((bb * NHEADS + hh) * SEQ) + t0) * HDIM + d0;
                float2 v;
                v.x = acc[mt][nt][0] + b0v; v.y = acc[mt][nt][1] + b1v;
                *(float2*)p = v;
                v.x = acc[mt][nt][2] + b0v; v.y = acc[mt][nt][3] + b1v;
                *(float2*)(p + 8 * HDIM) = v;      // row0+8, same batch/head
            }
    }
#undef LOAD_STAGE
#undef STORE_STAGE
#undef COMPUTE
}

// ---------------------------------------------------------------------------
// Sliding-window attention, lane-per-key QK + packed-f32x2 PV. (unchanged, R8)
// ---------------------------------------------------------------------------
#define KPAD 68
#define P64  66

__global__ __launch_bounds__(128) void attn_kernel()
{
    extern __shared__ float sm[];
    float* Qs = sm;                      // [64][KPAD]
    float* Ks = sm + 64 * KPAD;          // [128][KPAD]
    float* Vs = sm + (64 + 128) * KPAD;  // [128][KPAD]
    unsigned long long* Ps =
        (unsigned long long*)(sm + (64 + 256) * KPAD);

    const int q0 = blockIdx.x * 64;
    const int h  = blockIdx.y;
    const int b  = blockIdx.z;

    const size_t bh = (size_t)(b * NHEADS + h) * SEQ * HDIM;
    const float* Qg = g_Q + bh;
    const float* Kg = g_K + bh;
    const float* Vg = g_V + bh;

    const int tid = threadIdx.x;

    for (int it = tid; it < 64 * 16; it += 128) {
        const int r  = it >> 4;
        const int cv = (it & 15) << 2;
        float4 qv = *(const float4*)(Qg + (size_t)(q0 + r) * HDIM + cv);
        *(float4*)(Qs + r * KPAD + cv) = qv;
    }
    for (int it = tid; it < 128 * 16; it += 128) {
        const int r  = it >> 4;
        const int cv = (it & 15) << 2;
        const int jg = q0 + r;
        float4 kv, vv;
        if (jg < SEQ) {
            kv = *(const float4*)(Kg + (size_t)jg * HDIM + cv);
            vv = *(const float4*)(Vg + (size_t)jg * HDIM + cv);
        } else {
            kv = make_float4(0.f, 0.f, 0.f, 0.f);
            vv = kv;
        }
        *(float4*)(Ks + r * KPAD + cv) = kv;
        *(float4*)(Vs + r * KPAD + cv) = vv;
    }
    __syncthreads();

    const int w    = tid >> 5;
    const int lane = tid & 31;
    const unsigned FULL = 0xffffffffu;
    const float NEG_INF = -__int_as_float(0x7f800000);
    unsigned long long* pw = Ps + w * P64;

    for (int qq = 0; qq < 16; ++qq) {
        const int i_loc = w * 16 + qq;
        const int i     = q0 + i_loc;
        const int nvalid = min(HALFWIN, SEQ - 1 - i);
        const ulonglong2* qp = (const ulonglong2*)(Qs + i_loc * KPAD);

        float s[3];
#pragma unroll
        for (int c = 0; c < 3; ++c) {
            const int idx = c * 32 + lane;
            const int row = min(i_loc + idx, 127);
            const ulonglong2* kp = (const ulonglong2*)(Ks + row * KPAD);
            unsigned long long acc2 = 0ULL;
#pragma unroll
            for (int d8 = 0; d8 < 16; ++d8) {
                ulonglong2 kq = kp[d8];
                ulonglong2 qd = qp[d8];
                fma2(acc2, qd.x, kq.x);
                fma2(acc2, qd.y, kq.y);
            }
            float alo, ahi;
            unpack2(acc2, alo, ahi);
            float sc = (alo + ahi) * 0.125f;
            s[c] = (idx > nvalid) ? NEG_INF : sc;
        }

        float m = fmaxf(fmaxf(s[0], s[1]), s[2]);
#pragma unroll
        for (int off = 16; off; off >>= 1)
            m = fmaxf(m, __shfl_xor_sync(FULL, m, off));
        const float p0 = __expf(s[0] - m);
        const float p1 = __expf(s[1] - m);
        const float p2 = __expf(s[2] - m);
        float sum = p0 + p1 + p2;
#pragma unroll
        for (int off = 16; off; off >>= 1)
            sum += __shfl_xor_sync(FULL, sum, off);
        const float inv = 1.0f / sum;

        __syncwarp();
        {
            const float P0 = p0 * inv, P1 = p1 * inv;
            pw[lane]      = pack2(P0, P0);
            pw[lane + 32] = pack2(P1, P1);
            if (lane == 0) { const float P2 = p2 * inv; pw[64] = pack2(P2, P2); }
        }
        __syncwarp();

        unsigned long long o2 = 0ULL;
        const float* vbase = Vs + i_loc * KPAD + 2 * lane;
#pragma unroll 8
        for (int j = 0; j < 64; ++j) {
            unsigned long long v2 = *(const unsigned long long*)(vbase + j * KPAD);
            fma2(o2, pw[j], v2);
        }
        {
            unsigned long long v2 = *(const unsigned long long*)(vbase + 64 * KPAD);
            fma2(o2, pw[64], v2);
        }

        float* op = g_attn + ((size_t)(b * SEQ + i)) * DMODEL + h * HDIM;
        *(unsigned long long*)(op + 2 * lane) = o2;
    }
}

// ---------------------------------------------------------------------------
extern "C" void kernel_launch(void* const* d_in, const int* in_sizes, int n_in,
                              void* d_out, int out_size)
{
    (void)in_sizes; (void)n_in; (void)out_size;
    const float* x      = (const float*)d_in[0];
    const float* w_qkv  = (const float*)d_in[1];
    const float* b_qkv  = (const float*)d_in[2];
    const float* w_out  = (const float*)d_in[3];
    const float* b_out  = (const float*)d_in[4];
    float* out = (float*)d_out;

    void* attn_sym = nullptr;
    cudaGetSymbolAddress(&attn_sym, g_attn);

    const int GEMM_SMEM = 4 * 2 * TILE_U32 * 4;   // 81920 B
    cudaFuncSetAttribute(gemm_bf16x3,
                         cudaFuncAttributeMaxDynamicSharedMemorySize, GEMM_SMEM);
    const int ATTN_SMEM = (64 + 128 + 128) * KPAD * 4 + 4 * P64 * 8;
    cudaFuncSetAttribute(attn_kernel,
                         cudaFuncAttributeMaxDynamicSharedMemorySize, ATTN_SMEM);

    const int M = BATCH * SEQ;  // 4096

    // 1) QKV projection -> g_Q/g_K/g_V [b,h,t,d]
    dim3 g1((3 * DMODEL) / 128, M / 128);
    gemm_bf16x3<<<g1, 256, GEMM_SMEM>>>(x, w_qkv, b_qkv, nullptr,
                                        3 * DMODEL, DMODEL, 1);

    // 2) Windowed attention -> g_attn [b,t,h*64+d]
    dim3 g2(SEQ / 64, NHEADS, BATCH);
    attn_kernel<<<g2, 128, ATTN_SMEM>>>();

    // 3) Output projection -> d_out
    dim3 g3(DMODEL / 128, M / 128);
    gemm_bf16x3<<<g3, 256, GEMM_SMEM>>>((const float*)attn_sym, w_out, b_out, out,
                                        DMODEL, DMODEL, 0);
}

// round 11
// speedup vs baseline: 2.0885x; 1.0502x over previous
#include <cuda_runtime.h>
#include <cuda_bf16.h>
#include <math.h>

// Problem constants
#define BATCH 2
#define SEQ   2048
#define DMODEL 1024
#define NHEADS 16
#define HDIM  64
#define HALFWIN 64          // keys j in [i, i+64]  (<=65 keys per query)
#define KP    (DMODEL / 2)  // packed u32 per row (bf16x2 pairs) = 512

// Scratch (allocation-free rule: __device__ globals)
__device__ float g_Q[BATCH * NHEADS * SEQ * HDIM];     // [b,h,t,d]
__device__ float g_K[BATCH * NHEADS * SEQ * HDIM];
__device__ float g_V[BATCH * NHEADS * SEQ * HDIM];

// Pre-split packed bf16x2 operands (hi/lo residuals), row-major [rows][KP]
__device__ unsigned g_xs_hi  [BATCH * SEQ * KP];       // x          4096 rows
__device__ unsigned g_xs_lo  [BATCH * SEQ * KP];
__device__ unsigned g_wqkv_hi[3 * DMODEL * KP];        // w_qkv      3072 rows
__device__ unsigned g_wqkv_lo[3 * DMODEL * KP];
__device__ unsigned g_wout_hi[DMODEL * KP];            // w_out      1024 rows
__device__ unsigned g_wout_lo[DMODEL * KP];
__device__ unsigned g_attn_hi[BATCH * SEQ * KP];       // attn out   4096 rows
__device__ unsigned g_attn_lo[BATCH * SEQ * KP];

// ---- packed f32x2 helpers (attention) ----
__device__ __forceinline__ unsigned long long pack2(float lo, float hi) {
    unsigned long long r;
    asm("mov.b64 %0, {%1, %2};" : "=l"(r) : "f"(lo), "f"(hi));
    return r;
}
__device__ __forceinline__ void unpack2(unsigned long long v, float& lo, float& hi) {
    asm("mov.b64 {%0, %1}, %2;" : "=f"(lo), "=f"(hi) : "l"(v));
}
__device__ __forceinline__ void fma2(unsigned long long& d,
                                     unsigned long long a, unsigned long long b) {
    asm("fma.rn.f32x2 %0, %1, %2, %0;" : "+l"(d) : "l"(a), "l"(b));
}

// ---- bf16 split: (f0,f1) -> packed hi pair + packed lo-residual pair ----
__device__ __forceinline__ void split2(float f0, float f1,
                                       unsigned& hi, unsigned& lo) {
    __nv_bfloat16 h0 = __float2bfloat16_rn(f0);
    __nv_bfloat16 h1 = __float2bfloat16_rn(f1);
    float r0 = f0 - __bfloat162float(h0);
    float r1 = f1 - __bfloat162float(h1);
    __nv_bfloat16 l0 = __float2bfloat16_rn(r0);
    __nv_bfloat16 l1 = __float2bfloat16_rn(r1);
    __nv_bfloat162 hp = __halves2bfloat162(h0, h1);   // low 16b = even-k elem
    __nv_bfloat162 lp = __halves2bfloat162(l0, l1);
    hi = *reinterpret_cast<unsigned*>(&hp);
    lo = *reinterpret_cast<unsigned*>(&lp);
}

__device__ __forceinline__ void mma_bf16(float* d,
    unsigned a0, unsigned a1, unsigned a2, unsigned a3,
    unsigned b0, unsigned b1)
{
    asm("mma.sync.aligned.m16n8k16.row.col.f32.bf16.bf16.f32 "
        "{%0,%1,%2,%3}, {%4,%5,%6,%7}, {%8,%9}, {%0,%1,%2,%3};"
        : "+f"(d[0]), "+f"(d[1]), "+f"(d[2]), "+f"(d[3])
        : "r"(a0), "r"(a1), "r"(a2), "r"(a3), "r"(b0), "r"(b1));
}

// ---- cp.async helpers ----
__device__ __forceinline__ void cp16(unsigned sa, const void* g) {
    asm volatile("cp.async.ca.shared.global [%0], [%1], 16;" :: "r"(sa), "l"(g));
}
#define CP_COMMIT() asm volatile("cp.async.commit_group;")
#define CP_WAIT1()  asm volatile("cp.async.wait_group 1;")
#define CP_WAIT0()  asm volatile("cp.async.wait_group 0;")

// ---------------------------------------------------------------------------
// Pre-split: fp32 row-major -> packed bf16x2 hi/lo arrays. 1 float4 / thread.
// ---------------------------------------------------------------------------
__global__ __launch_bounds__(256) void split_kernel(
    const float* __restrict__ src,
    unsigned* __restrict__ hi, unsigned* __restrict__ lo, int n4)
{
    const int idx = blockIdx.x * 256 + threadIdx.x;
    if (idx >= n4) return;
    float4 v = ((const float4*)src)[idx];
    unsigned h0, l0, h1, l1;
    split2(v.x, v.y, h0, l0);
    split2(v.z, v.w, h1, l1);
    ((uint2*)hi)[idx] = make_uint2(h0, h1);
    ((uint2*)lo)[idx] = make_uint2(l0, l1);
}

// ---------------------------------------------------------------------------
// NT GEMM on tensor cores, bf16x3 split, pre-packed operands.
// C[m,n] = sum_k A[m,k]*W[n,k] + bias[n]; A/W given as packed hi/lo [rows][KP].
// CTA 128x128, BK=32 (16 u32), 256 thr = 8 warps (2m x 4n), cp.async 2-stage.
// PSTR=20 u32 row stride (16 payload + 4 pad): conflict-free fragment LDS.
// mode 0: C row-major (+bias); mode 1: QKV scatter into g_{Q,K,V} (+bias).
// ---------------------------------------------------------------------------
#define PSTR 20
#define TILE_U32 (128 * PSTR)          // 2560 u32 per array per buffer

__global__ __launch_bounds__(256, 2) void gemm_bf16x3(
    const unsigned* __restrict__ Ahi, const unsigned* __restrict__ Alo,
    const unsigned* __restrict__ Whi, const unsigned* __restrict__ Wlo,
    const float* __restrict__ bias, float* __restrict__ C,
    int N, int mode)
{
    extern __shared__ unsigned smem_u[];
    unsigned* sAhi = smem_u;                    // [2][TILE_U32]
    unsigned* sAlo = sAhi + 2 * TILE_U32;
    unsigned* sWhi = sAlo + 2 * TILE_U32;
    unsigned* sWlo = sWhi + 2 * TILE_U32;

    const unsigned aAhi = (unsigned)__cvta_generic_to_shared(sAhi);
    const unsigned aAlo = (unsigned)__cvta_generic_to_shared(sAlo);
    const unsigned aWhi = (unsigned)__cvta_generic_to_shared(sWhi);
    const unsigned aWlo = (unsigned)__cvta_generic_to_shared(sWlo);

    const int tid = threadIdx.x;
    const int m0 = blockIdx.y * 128;
    const int n0 = blockIdx.x * 128;

    // Staging map: thread handles chunks c0=2*tid, c1=2*tid+1 of each array.
    // chunk c: row = c>>2 (0..127), u32 pos = (c&3)*4.
    const int c0 = tid * 2, c1 = c0 + 1;
    const int r0s = c0 >> 2, p0s = (c0 & 3) << 2;
    const int r1s = c1 >> 2, p1s = (c1 & 3) << 2;
    const unsigned so0 = r0s * PSTR + p0s;      // smem u32 offset within buffer
    const unsigned so1 = r1s * PSTR + p1s;

    const unsigned* pAhi0 = Ahi + (size_t)(m0 + r0s) * KP + p0s;
    const unsigned* pAhi1 = Ahi + (size_t)(m0 + r1s) * KP + p1s;
    const unsigned* pAlo0 = Alo + (size_t)(m0 + r0s) * KP + p0s;
    const unsigned* pAlo1 = Alo + (size_t)(m0 + r1s) * KP + p1s;
    const unsigned* pWhi0 = Whi + (size_t)(n0 + r0s) * KP + p0s;
    const unsigned* pWhi1 = Whi + (size_t)(n0 + r1s) * KP + p1s;
    const unsigned* pWlo0 = Wlo + (size_t)(n0 + r0s) * KP + p0s;
    const unsigned* pWlo1 = Wlo + (size_t)(n0 + r1s) * KP + p1s;

    const int wid  = tid >> 5;
    const int lane = tid & 31;
    const int wm = wid >> 2, wn = wid & 3;      // 2 x 4 warp grid
    const int mbase = wm * 64, nbase = wn * 32;
    const int g  = lane >> 2;                   // 0..7
    const int t4 = lane & 3;                    // 0..3

    float acc[4][4][4];
#pragma unroll
    for (int mt = 0; mt < 4; ++mt)
#pragma unroll
        for (int nt = 0; nt < 4; ++nt)
#pragma unroll
            for (int r = 0; r < 4; ++r) acc[mt][nt][r] = 0.0f;

#define ISSUE(kt, bf)  do {                                       \
        const int ko = (kt) * 16;                                 \
        const unsigned bo = (bf) * TILE_U32;                      \
        cp16(aAhi + 4 * (bo + so0), pAhi0 + ko);                  \
        cp16(aAhi + 4 * (bo + so1), pAhi1 + ko);                  \
        cp16(aAlo + 4 * (bo + so0), pAlo0 + ko);                  \
        cp16(aAlo + 4 * (bo + so1), pAlo1 + ko);                  \
        cp16(aWhi + 4 * (bo + so0), pWhi0 + ko);                  \
        cp16(aWhi + 4 * (bo + so1), pWhi1 + ko);                  \
        cp16(aWlo + 4 * (bo + so0), pWlo0 + ko);                  \
        cp16(aWlo + 4 * (bo + so1), pWlo1 + ko);                  \
        CP_COMMIT();  } while (0)

#define COMPUTE(buf)  do {                                        \
        const unsigned* bAh = sAhi + (buf) * TILE_U32;            \
        const unsigned* bAl = sAlo + (buf) * TILE_U32;            \
        const unsigned* bWh = sWhi + (buf) * TILE_U32;            \
        const unsigned* bWl = sWlo + (buf) * TILE_U32;            \
        _Pragma("unroll")                                         \
        for (int s = 0; s < 2; ++s) {                             \
            const int cs = s * 8 + t4;                            \
            unsigned bh0[4], bh1[4], bl0[4], bl1[4];              \
            _Pragma("unroll")                                     \
            for (int nt = 0; nt < 4; ++nt) {                      \
                const int rb = (nbase + nt * 8 + g) * PSTR + cs;  \
                bh0[nt] = bWh[rb];     bh1[nt] = bWh[rb + 4];     \
                bl0[nt] = bWl[rb];     bl1[nt] = bWl[rb + 4];     \
            }                                                     \
            _Pragma("unroll")                                     \
            for (int mt = 0; mt < 4; ++mt) {                      \
                const int q0i = (mbase + mt * 16 + g) * PSTR + cs;\
                const int q1i = q0i + 8 * PSTR;                   \
                unsigned ah0 = bAh[q0i],   ah1 = bAh[q1i];        \
                unsigned ah2 = bAh[q0i+4], ah3 = bAh[q1i+4];      \
                unsigned al0 = bAl[q0i],   al1 = bAl[q1i];        \
                unsigned al2 = bAl[q0i+4], al3 = bAl[q1i+4];      \
                _Pragma("unroll")                                 \
                for (int nt = 0; nt < 4; ++nt) {                  \
                    mma_bf16(acc[mt][nt], ah0,ah1,ah2,ah3, bh0[nt], bh1[nt]); \
                    mma_bf16(acc[mt][nt], ah0,ah1,ah2,ah3, bl0[nt], bl1[nt]); \
                    mma_bf16(acc[mt][nt], al0,al1,al2,al3, bh0[nt], bh1[nt]); \
                } } } } while (0)

    const int ntiles = KP >> 4;                 // 32

    // 2-stage cp.async pipeline
    ISSUE(0, 0);
    ISSUE(1, 1);
    CP_WAIT1();
    __syncthreads();

    int buf = 0;
    for (int kt = 0; kt < ntiles; ++kt) {
        COMPUTE(buf);
        if (kt + 2 < ntiles) {
            __syncthreads();                    // done reading buf
            ISSUE(kt + 2, buf);
            CP_WAIT1();                         // tile kt+1 resident
            __syncthreads();
        } else if (kt + 1 < ntiles) {
            CP_WAIT0();
            __syncthreads();
        }
        buf ^= 1;
    }

    // ---- epilogue ----
    if (mode == 0) {
#pragma unroll
        for (int mt = 0; mt < 4; ++mt)
#pragma unroll
            for (int nt = 0; nt < 4; ++nt) {
                const int row0 = m0 + mbase + mt * 16 + g;
                const int col  = n0 + nbase + nt * 8 + 2 * t4;
                const float b0v = bias[col], b1v = bias[col + 1];
                float2 v;
                v.x = acc[mt][nt][0] + b0v; v.y = acc[mt][nt][1] + b1v;
                *(float2*)(C + (size_t)row0 * N + col) = v;
                v.x = acc[mt][nt][2] + b0v; v.y = acc[mt][nt][3] + b1v;
                *(float2*)(C + (size_t)(row0 + 8) * N + col) = v;
            }
    } else {
        const int cgrp = n0 >> 10;                 // 0=Q,1=K,2=V (CTA-constant)
        float* dst = (cgrp == 0) ? g_Q : (cgrp == 1) ? g_K : g_V;
        const int bb = m0 >> 11;                   // batch (CTA-constant)
#pragma unroll
        for (int mt = 0; mt < 4; ++mt)
#pragma unroll
            for (int nt = 0; nt < 4; ++nt) {
                const int col = n0 + nbase + nt * 8 + 2 * t4;
                const int hh  = (col >> 6) & (NHEADS - 1);
                const int d0  = col & (HDIM - 1);
                const float b0v = bias[col], b1v = bias[col + 1];
                const int row0 = m0 + mbase + mt * 16 + g;
                const int t0   = row0 & (SEQ - 1);
                float* p = dst + ((size_t)((bb * NHEADS + hh) * SEQ) + t0) * HDIM + d0;
                float2 v;
                v.x = acc[mt][nt][0] + b0v; v.y = acc[mt][nt][1] + b1v;
                *(float2*)p = v;
                v.x = acc[mt][nt][2] + b0v; v.y = acc[mt][nt][3] + b1v;
                *(float2*)(p + 8 * HDIM) = v;      // row0+8, same batch/head
            }
    }
#undef ISSUE
#undef COMPUTE
}

// ---------------------------------------------------------------------------
// Sliding-window attention, lane-per-key QK + packed-f32x2 PV.
// Output written pre-split (hi/lo packed bf16x2) for the projection GEMM.
// ---------------------------------------------------------------------------
#define KPAD 68
#define P64  66

__global__ __launch_bounds__(128) void attn_kernel()
{
    extern __shared__ float sm[];
    float* Qs = sm;                      // [64][KPAD]
    float* Ks = sm + 64 * KPAD;          // [128][KPAD]
    float* Vs = sm + (64 + 128) * KPAD;  // [128][KPAD]
    unsigned long long* Ps =
        (unsigned long long*)(sm + (64 + 256) * KPAD);

    const int q0   = blockIdx.x * 64;
    const int head = blockIdx.y;
    const int b    = blockIdx.z;

    const size_t bh = (size_t)(b * NHEADS + head) * SEQ * HDIM;
    const float* Qg = g_Q + bh;
    const float* Kg = g_K + bh;
    const float* Vg = g_V + bh;

    const int tid = threadIdx.x;

    for (int it = tid; it < 64 * 16; it += 128) {
        const int r  = it >> 4;
        const int cv = (it & 15) << 2;
        float4 qv = *(const float4*)(Qg + (size_t)(q0 + r) * HDIM + cv);
        *(float4*)(Qs + r * KPAD + cv) = qv;
    }
    for (int it = tid; it < 128 * 16; it += 128) {
        const int r  = it >> 4;
        const int cv = (it & 15) << 2;
        const int jg = q0 + r;
        float4 kv, vv;
        if (jg < SEQ) {
            kv = *(const float4*)(Kg + (size_t)jg * HDIM + cv);
            vv = *(const float4*)(Vg + (size_t)jg * HDIM + cv);
        } else {
            kv = make_float4(0.f, 0.f, 0.f, 0.f);
            vv = kv;
        }
        *(float4*)(Ks + r * KPAD + cv) = kv;
        *(float4*)(Vs + r * KPAD + cv) = vv;
    }
    __syncthreads();

    const int w    = tid >> 5;
    const int lane = tid & 31;
    const unsigned FULL = 0xffffffffu;
    const float NEG_INF = -__int_as_float(0x7f800000);
    unsigned long long* pw = Ps + w * P64;

    for (int qq = 0; qq < 16; ++qq) {
        const int i_loc = w * 16 + qq;
        const int i     = q0 + i_loc;
        const int nvalid = min(HALFWIN, SEQ - 1 - i);
        const ulonglong2* qp = (const ulonglong2*)(Qs + i_loc * KPAD);

        float s[3];
#pragma unroll
        for (int c = 0; c < 3; ++c) {
            const int idx = c * 32 + lane;
            const int row = min(i_loc + idx, 127);
            const ulonglong2* kp = (const ulonglong2*)(Ks + row * KPAD);
            unsigned long long acc2 = 0ULL;
#pragma unroll
            for (int d8 = 0; d8 < 16; ++d8) {
                ulonglong2 kq = kp[d8];
                ulonglong2 qd = qp[d8];
                fma2(acc2, qd.x, kq.x);
                fma2(acc2, qd.y, kq.y);
            }
            float alo, ahi;
            unpack2(acc2, alo, ahi);
            float sc = (alo + ahi) * 0.125f;
            s[c] = (idx > nvalid) ? NEG_INF : sc;
        }

        float m = fmaxf(fmaxf(s[0], s[1]), s[2]);
#pragma unroll
        for (int off = 16; off; off >>= 1)
            m = fmaxf(m, __shfl_xor_sync(FULL, m, off));
        const float p0 = __expf(s[0] - m);
        const float p1 = __expf(s[1] - m);
        const float p2 = __expf(s[2] - m);
        float sum = p0 + p1 + p2;
#pragma unroll
        for (int off = 16; off; off >>= 1)
            sum += __shfl_xor_sync(FULL, sum, off);
        const float inv = 1.0f / sum;

        __syncwarp();
        {
            const float P0 = p0 * inv, P1 = p1 * inv;
            pw[lane]      = pack2(P0, P0);
            pw[lane + 32] = pack2(P1, P1);
            if (lane == 0) { const float P2 = p2 * inv; pw[64] = pack2(P2, P2); }
        }
        __syncwarp();

        unsigned long long o2 = 0ULL;
        const float* vbase = Vs + i_loc * KPAD + 2 * lane;
#pragma unroll 8
        for (int j = 0; j < 64; ++j) {
            unsigned long long v2 = *(const unsigned long long*)(vbase + j * KPAD);
            fma2(o2, pw[j], v2);
        }
        {
            unsigned long long v2 = *(const unsigned long long*)(vbase + 64 * KPAD);
            fma2(o2, pw[64], v2);
        }

        // Emit pre-split packed output: lane owns dims (2*lane, 2*lane+1)
        // = one k-even/odd bf16x2 pair of the projection GEMM's K dim.
        float f0, f1;
        unpack2(o2, f0, f1);
        unsigned hi32, lo32;
        split2(f0, f1, hi32, lo32);
        const size_t orow = (size_t)(b * SEQ + i) * KP + head * 32 + lane;
        g_attn_hi[orow] = hi32;
        g_attn_lo[orow] = lo32;
    }
}

// ---------------------------------------------------------------------------
extern "C" void kernel_launch(void* const* d_in, const int* in_sizes, int n_in,
                              void* d_out, int out_size)
{
    (void)in_sizes; (void)n_in; (void)out_size;
    const float* x      = (const float*)d_in[0];
    const float* w_qkv  = (const float*)d_in[1];
    const float* b_qkv  = (const float*)d_in[2];
    const float* w_out  = (const float*)d_in[3];
    const float* b_out  = (const float*)d_in[4];
    float* out = (float*)d_out;

    void *xs_hi, *xs_lo, *wq_hi, *wq_lo, *wo_hi, *wo_lo, *at_hi, *at_lo;
    cudaGetSymbolAddress(&xs_hi, g_xs_hi);   cudaGetSymbolAddress(&xs_lo, g_xs_lo);
    cudaGetSymbolAddress(&wq_hi, g_wqkv_hi); cudaGetSymbolAddress(&wq_lo, g_wqkv_lo);
    cudaGetSymbolAddress(&wo_hi, g_wout_hi); cudaGetSymbolAddress(&wo_lo, g_wout_lo);
    cudaGetSymbolAddress(&at_hi, g_attn_hi); cudaGetSymbolAddress(&at_lo, g_attn_lo);

    const int GEMM_SMEM = 4 * 2 * TILE_U32 * 4;   // 81920 B
    cudaFuncSetAttribute(gemm_bf16x3,
                         cudaFuncAttributeMaxDynamicSharedMemorySize, GEMM_SMEM);
    const int ATTN_SMEM = (64 + 128 + 128) * KPAD * 4 + 4 * P64 * 8;
    cudaFuncSetAttribute(attn_kernel,
                         cudaFuncAttributeMaxDynamicSharedMemorySize, ATTN_SMEM);

    const int M = BATCH * SEQ;  // 4096

    // 0) Pre-split fp32 -> packed bf16x2 hi/lo
    {
        int n4 = M * DMODEL / 4;                  // x: 1048576
        split_kernel<<<n4 / 256, 256>>>(x, (unsigned*)xs_hi, (unsigned*)xs_lo, n4);
        n4 = 3 * DMODEL * DMODEL / 4;             // w_qkv: 786432
        split_kernel<<<n4 / 256, 256>>>(w_qkv, (unsigned*)wq_hi, (unsigned*)wq_lo, n4);
        n4 = DMODEL * DMODEL / 4;                 // w_out: 262144
        split_kernel<<<n4 / 256, 256>>>(w_out, (unsigned*)wo_hi, (unsigned*)wo_lo, n4);
    }

    // 1) QKV projection -> g_Q/g_K/g_V [b,h,t,d]
    dim3 g1((3 * DMODEL) / 128, M / 128);
    gemm_bf16x3<<<g1, 256, GEMM_SMEM>>>(
        (const unsigned*)xs_hi, (const unsigned*)xs_lo,
        (const unsigned*)wq_hi, (const unsigned*)wq_lo,
        b_qkv, nullptr, 3 * DMODEL, 1);

    // 2) Windowed attention -> g_attn_{hi,lo} packed [b*t][KP]
    dim3 g2(SEQ / 64, NHEADS, BATCH);
    attn_kernel<<<g2, 128, ATTN_SMEM>>>();

    // 3) Output projection -> d_out
    dim3 g3(DMODEL / 128, M / 128);
    gemm_bf16x3<<<g3, 256, GEMM_SMEM>>>(
        (const unsigned*)at_hi, (const unsigned*)at_lo,
        (const unsigned*)wo_hi, (const unsigned*)wo_lo,
        b_out, out, DMODEL, 0);
}

// round 15
// speedup vs baseline: 2.2664x; 1.0852x over previous
#include <cuda_runtime.h>
#include <cuda_bf16.h>
#include <math.h>
#include <stdint.h>

// Problem constants
#define BATCH 2
#define SEQ   2048
#define DMODEL 1024
#define NHEADS 16
#define HDIM  64
#define HALFWIN 64          // keys j in [i, i+64]  (<=65 keys per query)
#define KP    (DMODEL / 2)  // packed u32 per row (bf16x2 pairs) = 512

// Scratch (allocation-free rule: __device__ globals)
__device__ float g_Q[BATCH * NHEADS * SEQ * HDIM];     // [b,h,t,d]
__device__ float g_K[BATCH * NHEADS * SEQ * HDIM];
__device__ float g_V[BATCH * NHEADS * SEQ * HDIM];

// Pre-split packed bf16x2 operands (hi/lo residuals), row-major [rows][KP]
__device__ unsigned g_xs_hi  [BATCH * SEQ * KP];
__device__ unsigned g_xs_lo  [BATCH * SEQ * KP];
__device__ unsigned g_wqkv_hi[3 * DMODEL * KP];
__device__ unsigned g_wqkv_lo[3 * DMODEL * KP];
__device__ unsigned g_wout_hi[DMODEL * KP];
__device__ unsigned g_wout_lo[DMODEL * KP];
__device__ unsigned g_attn_hi[BATCH * SEQ * KP];
__device__ unsigned g_attn_lo[BATCH * SEQ * KP];

// ---- packed f32x2 helpers (attention) ----
__device__ __forceinline__ unsigned long long pack2(float lo, float hi) {
    unsigned long long r;
    asm("mov.b64 %0, {%1, %2};" : "=l"(r) : "f"(lo), "f"(hi));
    return r;
}
__device__ __forceinline__ void unpack2(unsigned long long v, float& lo, float& hi) {
    asm("mov.b64 {%0, %1}, %2;" : "=f"(lo), "=f"(hi) : "l"(v));
}
__device__ __forceinline__ void fma2(unsigned long long& d,
                                     unsigned long long a, unsigned long long b) {
    asm("fma.rn.f32x2 %0, %1, %2, %0;" : "+l"(d) : "l"(a), "l"(b));
}

// ---- bf16 split ----
__device__ __forceinline__ void split2(float f0, float f1,
                                       unsigned& hi, unsigned& lo) {
    __nv_bfloat16 h0 = __float2bfloat16_rn(f0);
    __nv_bfloat16 h1 = __float2bfloat16_rn(f1);
    float r0 = f0 - __bfloat162float(h0);
    float r1 = f1 - __bfloat162float(h1);
    __nv_bfloat16 l0 = __float2bfloat16_rn(r0);
    __nv_bfloat16 l1 = __float2bfloat16_rn(r1);
    __nv_bfloat162 hp = __halves2bfloat162(h0, h1);   // low 16b = even-k elem
    __nv_bfloat162 lp = __halves2bfloat162(l0, l1);
    hi = *reinterpret_cast<unsigned*>(&hp);
    lo = *reinterpret_cast<unsigned*>(&lp);
}

__device__ __forceinline__ void mma_bf16(float* d,
    unsigned a0, unsigned a1, unsigned a2, unsigned a3,
    unsigned b0, unsigned b1)
{
    asm("mma.sync.aligned.m16n8k16.row.col.f32.bf16.bf16.f32 "
        "{%0,%1,%2,%3}, {%4,%5,%6,%7}, {%8,%9}, {%0,%1,%2,%3};"
        : "+f"(d[0]), "+f"(d[1]), "+f"(d[2]), "+f"(d[3])
        : "r"(a0), "r"(a1), "r"(a2), "r"(a3), "r"(b0), "r"(b1));
}

// ---- ldmatrix / cp.async helpers ----
#define LDSM4(r0, r1, r2, r3, a)                                         \
    asm volatile("ldmatrix.sync.aligned.m8n8.x4.shared.b16 "             \
                 "{%0,%1,%2,%3}, [%4];"                                  \
                 : "=r"(r0), "=r"(r1), "=r"(r2), "=r"(r3) : "r"(a))

__device__ __forceinline__ void cp16(unsigned sa, const void* g) {
    asm volatile("cp.async.cg.shared.global [%0], [%1], 16;" :: "r"(sa), "l"(g));
}
#define CP_COMMIT() asm volatile("cp.async.commit_group;")
#define CP_WAIT1()  asm volatile("cp.async.wait_group 1;")
#define CP_WAIT0()  asm volatile("cp.async.wait_group 0;")

// ---------------------------------------------------------------------------
// Pre-split: fp32 row-major -> packed bf16x2 hi/lo arrays. 1 float4 / thread.
// ---------------------------------------------------------------------------
__global__ __launch_bounds__(256) void split_kernel(
    const float* __restrict__ src,
    unsigned* __restrict__ hi, unsigned* __restrict__ lo, int n4)
{
    const int idx = blockIdx.x * 256 + threadIdx.x;
    if (idx >= n4) return;
    float4 v = ((const float4*)src)[idx];
    unsigned h0, l0, h1, l1;
    split2(v.x, v.y, h0, l0);
    split2(v.z, v.w, h1, l1);
    ((uint2*)hi)[idx] = make_uint2(h0, h1);
    ((uint2*)lo)[idx] = make_uint2(l0, l1);
}

// ---------------------------------------------------------------------------
// NT GEMM on tensor cores (mma.sync), bf16x3 split, pre-packed operands,
// ldmatrix fragment loads.
// C[m,n] = sum_k A[m,k]*W[n,k] + bias[n]; A/W given as packed hi/lo [rows][KP].
// CTA 128x128, BK=32 (16 u32), 256 thr = 8 warps (2m x 4n), cp.async 2-stage.
// PSTR=20 u32 row stride: 16B-granule rows land on distinct banks for both
// cp.async stores and ldmatrix 8-address phases (20g+t mod 32 all-distinct).
// mode 0: C row-major (+bias); mode 1: QKV scatter into g_{Q,K,V} (+bias).
// ---------------------------------------------------------------------------
#define PSTR 20
#define TILE_U32 (128 * PSTR)          // 2560 u32 per array per buffer

__global__ __launch_bounds__(256, 2) void gemm_bf16x3(
    const unsigned* __restrict__ Ahi, const unsigned* __restrict__ Alo,
    const unsigned* __restrict__ Whi, const unsigned* __restrict__ Wlo,
    const float* __restrict__ bias, float* __restrict__ C,
    int N, int mode)
{
    extern __shared__ unsigned smem_u[];
    unsigned* sAhi = smem_u;                    // [2][TILE_U32]
    unsigned* sAlo = sAhi + 2 * TILE_U32;
    unsigned* sWhi = sAlo + 2 * TILE_U32;
    unsigned* sWlo = sWhi + 2 * TILE_U32;

    const unsigned aAhi = (unsigned)__cvta_generic_to_shared(sAhi);
    const unsigned aAlo = (unsigned)__cvta_generic_to_shared(sAlo);
    const unsigned aWhi = (unsigned)__cvta_generic_to_shared(sWhi);
    const unsigned aWlo = (unsigned)__cvta_generic_to_shared(sWlo);

    const int tid = threadIdx.x;
    const int m0 = blockIdx.y * 128;
    const int n0 = blockIdx.x * 128;

    // Staging map: thread handles chunks c0=2*tid, c1=2*tid+1 of each array.
    const int c0 = tid * 2, c1 = c0 + 1;
    const int r0s = c0 >> 2, p0s = (c0 & 3) << 2;
    const int r1s = c1 >> 2, p1s = (c1 & 3) << 2;
    const unsigned so0 = r0s * PSTR + p0s;
    const unsigned so1 = r1s * PSTR + p1s;

    const unsigned* pAhi0 = Ahi + (size_t)(m0 + r0s) * KP + p0s;
    const unsigned* pAhi1 = Ahi + (size_t)(m0 + r1s) * KP + p1s;
    const unsigned* pAlo0 = Alo + (size_t)(m0 + r0s) * KP + p0s;
    const unsigned* pAlo1 = Alo + (size_t)(m0 + r1s) * KP + p1s;
    const unsigned* pWhi0 = Whi + (size_t)(n0 + r0s) * KP + p0s;
    const unsigned* pWhi1 = Whi + (size_t)(n0 + r1s) * KP + p1s;
    const unsigned* pWlo0 = Wlo + (size_t)(n0 + r0s) * KP + p0s;
    const unsigned* pWlo1 = Wlo + (size_t)(n0 + r1s) * KP + p1s;

    const int wid  = tid >> 5;
    const int lane = tid & 31;
    const int wm = wid >> 2, wn = wid & 3;      // 2 x 4 warp grid
    const int mbase = wm * 64, nbase = wn * 32;
    const int g  = lane >> 2;                   // 0..7  (fragment row group)
    const int t4 = lane & 3;                    // 0..3

    // ldmatrix per-lane address offsets (u32 units within one array buffer)
    const int lr8 = lane & 7;
    const int lb  = (lane >> 3) & 1;
    const int lhi = lane >> 4;
    // A x4 tile (16 rows x k16): block0 rows0-7/k0-7, b1 rows8-15/k0-7,
    //                            b2 rows0-7/k8-15,  b3 rows8-15/k8-15
    unsigned offA[4];
#pragma unroll
    for (int mt = 0; mt < 4; ++mt)
        offA[mt] = (unsigned)((mbase + mt * 16 + lr8 + lb * 8) * PSTR + lhi * 4);
    // W x4 tile #p (nt = 2p, 2p+1): blocks (nt0,k0)(nt0,k8)(nt1,k0)(nt1,k8)
    unsigned offW[2];
#pragma unroll
    for (int p = 0; p < 2; ++p)
        offW[p] = (unsigned)((nbase + p * 16 + lhi * 8 + lr8) * PSTR + lb * 4);

    float acc[4][4][4];
#pragma unroll
    for (int mt = 0; mt < 4; ++mt)
#pragma unroll
        for (int nt = 0; nt < 4; ++nt)
#pragma unroll
            for (int r = 0; r < 4; ++r) acc[mt][nt][r] = 0.0f;

#define ISSUE(kt, bf)  do {                                       \
        const int ko = (kt) * 16;                                 \
        const unsigned bo = (bf) * TILE_U32;                      \
        cp16(aAhi + 4 * (bo + so0), pAhi0 + ko);                  \
        cp16(aAhi + 4 * (bo + so1), pAhi1 + ko);                  \
        cp16(aAlo + 4 * (bo + so0), pAlo0 + ko);                  \
        cp16(aAlo + 4 * (bo + so1), pAlo1 + ko);                  \
        cp16(aWhi + 4 * (bo + so0), pWhi0 + ko);                  \
        cp16(aWhi + 4 * (bo + so1), pWhi1 + ko);                  \
        cp16(aWlo + 4 * (bo + so0), pWlo0 + ko);                  \
        cp16(aWlo + 4 * (bo + so1), pWlo1 + ko);                  \
        CP_COMMIT();  } while (0)

#define COMPUTE(buf)  do {                                        \
        const unsigned bo = (unsigned)(buf) * (TILE_U32 * 4);     \
        _Pragma("unroll")                                         \
        for (int s = 0; s < 2; ++s) {                             \
            const unsigned sofs = bo + s * 32;                    \
            unsigned bh[8], bl[8];                                \
            LDSM4(bh[0], bh[1], bh[2], bh[3], aWhi + sofs + 4 * offW[0]); \
            LDSM4(bh[4], bh[5], bh[6], bh[7], aWhi + sofs + 4 * offW[1]); \
            LDSM4(bl[0], bl[1], bl[2], bl[3], aWlo + sofs + 4 * offW[0]); \
            LDSM4(bl[4], bl[5], bl[6], bl[7], aWlo + sofs + 4 * offW[1]); \
            _Pragma("unroll")                                     \
            for (int mt = 0; mt < 4; ++mt) {                      \
                unsigned ah[4], al[4];                            \
                LDSM4(ah[0], ah[1], ah[2], ah[3], aAhi + sofs + 4 * offA[mt]); \
                LDSM4(al[0], al[1], al[2], al[3], aAlo + sofs + 4 * offA[mt]); \
                _Pragma("unroll")                                 \
                for (int nt = 0; nt < 4; ++nt) {                  \
                    mma_bf16(acc[mt][nt], ah[0], ah[1], ah[2], ah[3], \
                             bh[2 * nt], bh[2 * nt + 1]);         \
                    mma_bf16(acc[mt][nt], ah[0], ah[1], ah[2], ah[3], \
                             bl[2 * nt], bl[2 * nt + 1]);         \
                    mma_bf16(acc[mt][nt], al[0], al[1], al[2], al[3], \
                             bh[2 * nt], bh[2 * nt + 1]);         \
                } } } } while (0)

    const int ntiles = KP >> 4;                 // 32

    // 2-stage cp.async pipeline
    ISSUE(0, 0);
    ISSUE(1, 1);
    CP_WAIT1();
    __syncthreads();

    int buf = 0;
    for (int kt = 0; kt < ntiles; ++kt) {
        COMPUTE(buf);
        if (kt + 2 < ntiles) {
            __syncthreads();                    // done reading buf
            ISSUE(kt + 2, buf);
            CP_WAIT1();                         // tile kt+1 resident
            __syncthreads();
        } else if (kt + 1 < ntiles) {
            CP_WAIT0();
            __syncthreads();
        }
        buf ^= 1;
    }

    // ---- epilogue ----
    if (mode == 0) {
#pragma unroll
        for (int mt = 0; mt < 4; ++mt)
#pragma unroll
            for (int nt = 0; nt < 4; ++nt) {
                const int row0 = m0 + mbase + mt * 16 + g;
                const int col  = n0 + nbase + nt * 8 + 2 * t4;
                const float b0v = bias[col], b1v = bias[col + 1];
                float2 v;
                v.x = acc[mt][nt][0] + b0v; v.y = acc[mt][nt][1] + b1v;
                *(float2*)(C + (size_t)row0 * N + col) = v;
                v.x = acc[mt][nt][2] + b0v; v.y = acc[mt][nt][3] + b1v;
                *(float2*)(C + (size_t)(row0 + 8) * N + col) = v;
            }
    } else {
        const int cgrp = n0 >> 10;                 // 0=Q,1=K,2=V (CTA-constant)
        float* dst = (cgrp == 0) ? g_Q : (cgrp == 1) ? g_K : g_V;
        const int bb = m0 >> 11;                   // batch (CTA-constant)
#pragma unroll
        for (int mt = 0; mt < 4; ++mt)
#pragma unroll
            for (int nt = 0; nt < 4; ++nt) {
                const int col = n0 + nbase + nt * 8 + 2 * t4;
                const int hh  = (col >> 6) & (NHEADS - 1);
                const int d0  = col & (HDIM - 1);
                const float b0v = bias[col], b1v = bias[col + 1];
                const int row0 = m0 + mbase + mt * 16 + g;
                const int t0   = row0 & (SEQ - 1);
                float* p = dst + ((size_t)((bb * NHEADS + hh) * SEQ) + t0) * HDIM + d0;
                float2 v;
                v.x = acc[mt][nt][0] + b0v; v.y = acc[mt][nt][1] + b1v;
                *(float2*)p = v;
                v.x = acc[mt][nt][2] + b0v; v.y = acc[mt][nt][3] + b1v;
                *(float2*)(p + 8 * HDIM) = v;      // row0+8, same batch/head
            }
    }
#undef ISSUE
#undef COMPUTE
}

// ---------------------------------------------------------------------------
// Sliding-window attention, lane-per-key QK + packed-f32x2 PV.
// Output written pre-split (hi/lo packed bf16x2) for the projection GEMM.
// ---------------------------------------------------------------------------
#define KPAD 68
#define P64  66

__global__ __launch_bounds__(128) void attn_kernel()
{
    extern __shared__ float sm[];
    float* Qs = sm;                      // [64][KPAD]
    float* Ks = sm + 64 * KPAD;          // [128][KPAD]
    float* Vs = sm + (64 + 128) * KPAD;  // [128][KPAD]
    unsigned long long* Ps =
        (unsigned long long*)(sm + (64 + 256) * KPAD);

    const int q0   = blockIdx.x * 64;
    const int head = blockIdx.y;
    const int b    = blockIdx.z;

    const size_t bh = (size_t)(b * NHEADS + head) * SEQ * HDIM;
    const float* Qg = g_Q + bh;
    const float* Kg = g_K + bh;
    const float* Vg = g_V + bh;

    const int tid = threadIdx.x;

    for (int it = tid; it < 64 * 16; it += 128) {
        const int r  = it >> 4;
        const int cv = (it & 15) << 2;
        float4 qv = *(const float4*)(Qg + (size_t)(q0 + r) * HDIM + cv);
        *(float4*)(Qs + r * KPAD + cv) = qv;
    }
    for (int it = tid; it < 128 * 16; it += 128) {
        const int r  = it >> 4;
        const int cv = (it & 15) << 2;
        const int jg = q0 + r;
        float4 kv, vv;
        if (jg < SEQ) {
            kv = *(const float4*)(Kg + (size_t)jg * HDIM + cv);
            vv = *(const float4*)(Vg + (size_t)jg * HDIM + cv);
        } else {
            kv = make_float4(0.f, 0.f, 0.f, 0.f);
            vv = kv;
        }
        *(float4*)(Ks + r * KPAD + cv) = kv;
        *(float4*)(Vs + r * KPAD + cv) = vv;
    }
    __syncthreads();

    const int w    = tid >> 5;
    const int lane = tid & 31;
    const unsigned FULL = 0xffffffffu;
    const float NEG_INF = -__int_as_float(0x7f800000);
    unsigned long long* pw = Ps + w * P64;

    for (int qq = 0; qq < 16; ++qq) {
        const int i_loc = w * 16 + qq;
        const int i     = q0 + i_loc;
        const int nvalid = min(HALFWIN, SEQ - 1 - i);
        const ulonglong2* qp = (const ulonglong2*)(Qs + i_loc * KPAD);

        float s[3];
#pragma unroll
        for (int c = 0; c < 3; ++c) {
            const int idx = c * 32 + lane;
            const int row = min(i_loc + idx, 127);
            const ulonglong2* kp = (const ulonglong2*)(Ks + row * KPAD);
            unsigned long long acc2 = 0ULL;
#pragma unroll
            for (int d8 = 0; d8 < 16; ++d8) {
                ulonglong2 kq = kp[d8];
                ulonglong2 qd = qp[d8];
                fma2(acc2, qd.x, kq.x);
                fma2(acc2, qd.y, kq.y);
            }
            float alo, ahi;
            unpack2(acc2, alo, ahi);
            float sc = (alo + ahi) * 0.125f;
            s[c] = (idx > nvalid) ? NEG_INF : sc;
        }

        float m = fmaxf(fmaxf(s[0], s[1]), s[2]);
#pragma unroll
        for (int off = 16; off; off >>= 1)
            m = fmaxf(m, __shfl_xor_sync(FULL, m, off));
        const float p0 = __expf(s[0] - m);
        const float p1 = __expf(s[1] - m);
        const float p2 = __expf(s[2] - m);
        float sum = p0 + p1 + p2;
#pragma unroll
        for (int off = 16; off; off >>= 1)
            sum += __shfl_xor_sync(FULL, sum, off);
        const float inv = 1.0f / sum;

        __syncwarp();
        {
            const float P0 = p0 * inv, P1 = p1 * inv;
            pw[lane]      = pack2(P0, P0);
            pw[lane + 32] = pack2(P1, P1);
            if (lane == 0) { const float P2 = p2 * inv; pw[64] = pack2(P2, P2); }
        }
        __syncwarp();

        unsigned long long o2 = 0ULL;
        const float* vbase = Vs + i_loc * KPAD + 2 * lane;
#pragma unroll 8
        for (int j = 0; j < 64; ++j) {
            unsigned long long v2 = *(const unsigned long long*)(vbase + j * KPAD);
            fma2(o2, pw[j], v2);
        }
        {
            unsigned long long v2 = *(const unsigned long long*)(vbase + 64 * KPAD);
            fma2(o2, pw[64], v2);
        }

        float f0, f1;
        unpack2(o2, f0, f1);
        unsigned hi32, lo32;
        split2(f0, f1, hi32, lo32);
        const size_t orow = (size_t)(b * SEQ + i) * KP + head * 32 + lane;
        g_attn_hi[orow] = hi32;
        g_attn_lo[orow] = lo32;
    }
}

// ---------------------------------------------------------------------------
extern "C" void kernel_launch(void* const* d_in, const int* in_sizes, int n_in,
                              void* d_out, int out_size)
{
    (void)in_sizes; (void)n_in; (void)out_size;
    const float* x      = (const float*)d_in[0];
    const float* w_qkv  = (const float*)d_in[1];
    const float* b_qkv  = (const float*)d_in[2];
    const float* w_out  = (const float*)d_in[3];
    const float* b_out  = (const float*)d_in[4];
    float* out = (float*)d_out;

    void *xs_hi, *xs_lo, *wq_hi, *wq_lo, *wo_hi, *wo_lo, *at_hi, *at_lo;
    cudaGetSymbolAddress(&xs_hi, g_xs_hi);   cudaGetSymbolAddress(&xs_lo, g_xs_lo);
    cudaGetSymbolAddress(&wq_hi, g_wqkv_hi); cudaGetSymbolAddress(&wq_lo, g_wqkv_lo);
    cudaGetSymbolAddress(&wo_hi, g_wout_hi); cudaGetSymbolAddress(&wo_lo, g_wout_lo);
    cudaGetSymbolAddress(&at_hi, g_attn_hi); cudaGetSymbolAddress(&at_lo, g_attn_lo);

    const int GEMM_SMEM = 4 * 2 * TILE_U32 * 4;   // 81920 B
    cudaFuncSetAttribute(gemm_bf16x3,
                         cudaFuncAttributeMaxDynamicSharedMemorySize, GEMM_SMEM);
    const int ATTN_SMEM = (64 + 128 + 128) * KPAD * 4 + 4 * P64 * 8;
    cudaFuncSetAttribute(attn_kernel,
                         cudaFuncAttributeMaxDynamicSharedMemorySize, ATTN_SMEM);

    const int M = BATCH * SEQ;  // 4096

    // 0) Pre-split fp32 -> packed bf16x2 hi/lo
    {
        int n4 = M * DMODEL / 4;
        split_kernel<<<n4 / 256, 256>>>(x, (unsigned*)xs_hi, (unsigned*)xs_lo, n4);
        n4 = 3 * DMODEL * DMODEL / 4;
        split_kernel<<<n4 / 256, 256>>>(w_qkv, (unsigned*)wq_hi, (unsigned*)wq_lo, n4);
        n4 = DMODEL * DMODEL / 4;
        split_kernel<<<n4 / 256, 256>>>(w_out, (unsigned*)wo_hi, (unsigned*)wo_lo, n4);
    }

    // 1) QKV projection -> g_Q/g_K/g_V [b,h,t,d]
    dim3 g1((3 * DMODEL) / 128, M / 128);
    gemm_bf16x3<<<g1, 256, GEMM_SMEM>>>(
        (const unsigned*)xs_hi, (const unsigned*)xs_lo,
        (const unsigned*)wq_hi, (const unsigned*)wq_lo,
        b_qkv, nullptr, 3 * DMODEL, 1);

    // 2) Windowed attention -> g_attn_{hi,lo} packed [b*t][KP]
    dim3 g2(SEQ / 64, NHEADS, BATCH);
    attn_kernel<<<g2, 128, ATTN_SMEM>>>();

    // 3) Output projection -> d_out
    dim3 g3(DMODEL / 128, M / 128);
    gemm_bf16x3<<<g3, 256, GEMM_SMEM>>>(
        (const unsigned*)at_hi, (const unsigned*)at_lo,
        (const unsigned*)wo_hi, (const unsigned*)wo_lo,
        b_out, out, DMODEL, 0);
}